// round 14
// baseline (speedup 1.0000x reference)
#include <cuda_runtime.h>
#include <cuda_bf16.h>
#include <math.h>
#include <stdint.h>

#define NB   4
#define CHN  256
#define NHW  4096
#define MALL 320   // 32 (b) + 32 (c) + 256 (d)

// ---- scratch (device globals -- allocation is forbidden) ----
// P is stored in fragment-tile order: [n][i-tile(32)][chunk(64)] tiles of
// 128 rows x 64 j; within a tile, 16B chunks ordered ((row>>3)*8+jt)*8+(row&7).
__device__ float         g_bcd[(size_t)NB * NHW * MALL];  // [n][i][320]
__device__ __nv_bfloat16 g_Phi[(size_t)NB * NHW * NHW];   // exp(s) hi (tiled)
__device__ __nv_bfloat16 g_Plo[(size_t)NB * NHW * NHW];   // exp(s) lo (tiled)
__device__ __nv_bfloat16 g_dhi[(size_t)NB * CHN * NHW];   // d^T hi  [n][c][j]
__device__ __nv_bfloat16 g_dlo[(size_t)NB * CHN * NHW];   // d^T lo

typedef unsigned long long ull;

__device__ __forceinline__ ull pack2(float lo, float hi) {
    ull r; asm("mov.b64 %0, {%1, %2};" : "=l"(r) : "f"(lo), "f"(hi)); return r;
}
__device__ __forceinline__ ull fma2(ull a, ull b, ull c) {
    ull d; asm("fma.rn.f32x2 %0, %1, %2, %3;" : "=l"(d) : "l"(a), "l"(b), "l"(c)); return d;
}
__device__ __forceinline__ float2 unpack2(ull v) {
    float2 f; asm("mov.b64 {%0, %1}, %2;" : "=f"(f.x), "=f"(f.y) : "l"(v)); return f;
}
__device__ __forceinline__ void cp_async16(uint32_t dst, const void* src) {
    asm volatile("cp.async.cg.shared.global [%0], [%1], 16;" :: "r"(dst), "l"(src));
}
#define CP_COMMIT() asm volatile("cp.async.commit_group;")
#define CP_WAIT0()  asm volatile("cp.async.wait_group 0;" ::: "memory")
#define CP_WAIT1()  asm volatile("cp.async.wait_group 1;" ::: "memory")

// warp-level bf16 tensor-core mma (baseline PTX, valid on sm_103 non-'a')
__device__ __forceinline__ void mma_bf16(float* d, const uint32_t* A,
                                         uint32_t b0, uint32_t b1) {
    asm volatile(
        "mma.sync.aligned.m16n8k16.row.col.f32.bf16.bf16.f32 "
        "{%0,%1,%2,%3}, {%4,%5,%6,%7}, {%8,%9}, {%0,%1,%2,%3};"
        : "+f"(d[0]), "+f"(d[1]), "+f"(d[2]), "+f"(d[3])
        : "r"(A[0]), "r"(A[1]), "r"(A[2]), "r"(A[3]), "r"(b0), "r"(b1));
}
__device__ __forceinline__ void ldsm_x4(uint32_t* r, uint32_t addr) {
    asm volatile("ldmatrix.sync.aligned.m8n8.x4.shared.b16 {%0,%1,%2,%3}, [%4];"
        : "=r"(r[0]), "=r"(r[1]), "=r"(r[2]), "=r"(r[3]) : "r"(addr));
}

// ---------------------------------------------------------------------------
// K1: fused 1x1 convs.  m-tile 16, 3 CTAs/SM.  Grid (8, 20, 4).
// ---------------------------------------------------------------------------
__global__ __launch_bounds__(256, 3) void k1_conv(
    const float* __restrict__ a,
    const float* __restrict__ b_w, const float* __restrict__ b_b,
    const float* __restrict__ c_w, const float* __restrict__ c_b,
    const float* __restrict__ d_w, const float* __restrict__ d_b)
{
    __shared__ float w_s[256][20];
    const int t  = threadIdx.x;
    const int n  = blockIdx.z;
    const int m0 = blockIdx.y * 16;
    const int i  = blockIdx.x * 512 + t;

#pragma unroll
    for (int k = 0; k < 16; k++) {
        int m = m0 + k;
        const float* wr = (m < 32) ? (b_w + m * 256)
                        : (m < 64) ? (c_w + (m - 32) * 256)
                                   : (d_w + (m - 64) * 256);
        w_s[t][k] = wr[t];
    }
    __syncthreads();

    ull acc[16];
#pragma unroll
    for (int q = 0; q < 8; q++) {
        int m = m0 + 2 * q;
        float bl = (m < 32) ? b_b[m] : (m < 64) ? c_b[m - 32] : d_b[m - 64];
        int m1 = m + 1;
        float bh = (m1 < 32) ? b_b[m1] : (m1 < 64) ? c_b[m1 - 32] : d_b[m1 - 64];
        acc[q] = pack2(bl, bh);
        acc[8 + q] = acc[q];
    }

    const float* ap = a + (size_t)n * CHN * NHW + i;
#pragma unroll 8
    for (int ch = 0; ch < 256; ch++) {
        float av0 = __ldg(ap + (size_t)ch * NHW);
        float av1 = __ldg(ap + (size_t)ch * NHW + 256);
        ull a20 = pack2(av0, av0);
        ull a21 = pack2(av1, av1);
        const ulonglong2* wrow = (const ulonglong2*)&w_s[ch][0];
#pragma unroll
        for (int q = 0; q < 4; q++) {
            ulonglong2 wv = wrow[q];
            acc[2 * q]         = fma2(a20, wv.x, acc[2 * q]);
            acc[2 * q + 1]     = fma2(a20, wv.y, acc[2 * q + 1]);
            acc[8 + 2 * q]     = fma2(a21, wv.x, acc[8 + 2 * q]);
            acc[8 + 2 * q + 1] = fma2(a21, wv.y, acc[8 + 2 * q + 1]);
        }
    }

#pragma unroll
    for (int p = 0; p < 2; p++) {
        float* outp = g_bcd + ((size_t)n * NHW + i + p * 256) * MALL + m0;
#pragma unroll
        for (int q = 0; q < 4; q++) {
            float2 x = unpack2(acc[8 * p + 2 * q]);
            float2 y = unpack2(acc[8 * p + 2 * q + 1]);
            ((float4*)outp)[q] = make_float4(x.x, x.y, y.x, y.y);
        }
    }
}

// ---------------------------------------------------------------------------
// KD: transpose + bf16-split d: g_bcd[n][j][64+c] -> d_hi/lo[n][c][j]
// ---------------------------------------------------------------------------
__global__ __launch_bounds__(256) void kd_split()
{
    __shared__ float ts[32][33];
    const int t  = threadIdx.x;
    const int n  = blockIdx.z;
    const int j0 = blockIdx.x * 32;
    const int c0 = blockIdx.y * 32;

#pragma unroll
    for (int k = 0; k < 4; k++) {
        int idx = t + k * 256;
        int jr = idx >> 5, cc = idx & 31;
        ts[jr][cc] = g_bcd[((size_t)(n * NHW) + j0 + jr) * MALL + 64 + c0 + cc];
    }
    __syncthreads();
#pragma unroll
    for (int k = 0; k < 4; k++) {
        int idx = t + k * 256;
        int cr = idx >> 5, jc = idx & 31;
        float v = ts[jc][cr];
        __nv_bfloat16 hi = __float2bfloat16(v);
        __nv_bfloat16 lo = __float2bfloat16(v - __bfloat162float(hi));
        size_t o = ((size_t)(n * CHN) + c0 + cr) * NHW + j0 + jc;
        g_dhi[o] = hi;
        g_dlo[o] = lo;
    }
}

// ---------------------------------------------------------------------------
// K2: scores via tensor cores (bf16 hi/lo 3-split, K=32) + fused exp.
// Direct fragment-tile-ordered stores: each warp store is 128B contiguous.
// 256 thr / 8 warps, tile 128i x 128j.  Grid (32 j-tiles, 32 i-tiles, 4).
// ---------------------------------------------------------------------------
#define K2RB 80   // staging rows: 64B data + 16B pad (conflict-free LDSM)

__global__ __launch_bounds__(256) void k2_scores()
{
    __shared__ __align__(16) char sm2[4 * 128 * K2RB];   // 40960 B
    const uint32_t smb = (uint32_t)__cvta_generic_to_shared(sm2);
    const int AHI = 0, ALO = 10240, BHI = 20480, BLO = 30720;

    const int t    = threadIdx.x;
    const int lane = t & 31;
    const int warp = t >> 5;
    const int g    = lane >> 2;
    const int tid  = lane & 3;
    const int iw   = warp & 3;      // 4 i-groups of 32
    const int cw   = warp >> 2;     // 2 j-groups of 64
    const int n    = blockIdx.z;
    const int i0   = blockIdx.y * 128;
    const int j0   = blockIdx.x * 128;

    // ---- staging: 128 q rows + 128 c rows of 32 fp32 -> bf16 hi/lo ----
    {
        const int r  = t >> 1;
        const int hb = t & 1;
        const float* qs = g_bcd + ((size_t)(n * NHW) + i0 + r) * MALL + hb * 16;
        const float* cs = g_bcd + ((size_t)(n * NHW) + j0 + r) * MALL + 32 + hb * 16;
        const uint32_t dst = (uint32_t)(r * K2RB + hb * 32);
#pragma unroll
        for (int sel = 0; sel < 2; sel++) {
            const float* src = sel ? cs : qs;
            const int OH = sel ? BHI : AHI;
            const int OL = sel ? BLO : ALO;
#pragma unroll
            for (int q = 0; q < 2; q++) {
                float4 v0 = *(const float4*)(src + q * 8);
                float4 v1 = *(const float4*)(src + q * 8 + 4);
                float f[8] = {v0.x, v0.y, v0.z, v0.w, v1.x, v1.y, v1.z, v1.w};
                union { __nv_bfloat16 b[8]; uint4 u; } H, L;
#pragma unroll
                for (int k = 0; k < 8; k++) {
                    H.b[k] = __float2bfloat16(f[k]);
                    L.b[k] = __float2bfloat16(f[k] - __bfloat162float(H.b[k]));
                }
                *(uint4*)(sm2 + OH + dst + q * 16) = H.u;
                *(uint4*)(sm2 + OL + dst + q * 16) = L.u;
            }
        }
    }
    __syncthreads();

    // ---- MMA: S[128 x 128] = q . c^T (3-split bf16) ----
    const uint32_t aAddr = smb + (uint32_t)((iw * 32 + (lane & 15)) * K2RB + (lane >> 4) * 16);
    const uint32_t bAddr = smb + (uint32_t)((cw * 64 + (lane >> 4) * 8 + (lane & 7)) * K2RB
                                            + ((lane >> 3) & 1) * 16);
    float d[2][8][4];
#pragma unroll
    for (int it = 0; it < 2; it++)
#pragma unroll
        for (int jt = 0; jt < 8; jt++)
#pragma unroll
            for (int r = 0; r < 4; r++) d[it][jt][r] = 0.0f;

#pragma unroll
    for (int ks = 0; ks < 2; ks++) {
        const uint32_t kb = ks * 32;
        uint32_t ah[2][4], al[2][4];
#pragma unroll
        for (int it = 0; it < 2; it++) {
            const uint32_t aa = aAddr + it * (16 * K2RB) + kb;
            ldsm_x4(ah[it], aa + AHI);
            ldsm_x4(al[it], aa + ALO);
        }
#pragma unroll
        for (int ctp = 0; ctp < 4; ctp++) {
            const int ct0 = 2 * ctp;
            const uint32_t ba = bAddr + ct0 * (8 * K2RB) + kb;
            uint32_t bh[4], bl[4];
            ldsm_x4(bh, ba + BHI);
            ldsm_x4(bl, ba + BLO);
            mma_bf16(d[0][ct0],     ah[0], bh[0], bh[1]);
            mma_bf16(d[1][ct0],     ah[1], bh[0], bh[1]);
            mma_bf16(d[0][ct0 + 1], ah[0], bh[2], bh[3]);
            mma_bf16(d[1][ct0 + 1], ah[1], bh[2], bh[3]);
            mma_bf16(d[0][ct0],     al[0], bh[0], bh[1]);
            mma_bf16(d[1][ct0],     al[1], bh[0], bh[1]);
            mma_bf16(d[0][ct0 + 1], al[0], bh[2], bh[3]);
            mma_bf16(d[1][ct0 + 1], al[1], bh[2], bh[3]);
            mma_bf16(d[0][ct0],     ah[0], bl[0], bl[1]);
            mma_bf16(d[1][ct0],     ah[1], bl[0], bl[1]);
            mma_bf16(d[0][ct0 + 1], ah[0], bl[2], bl[3]);
            mma_bf16(d[1][ct0 + 1], ah[1], bl[2], bl[3]);
        }
    }

    // ---- epilogue: exp + hi/lo split, fragment-tile-ordered stores ----
    // tile = [n][i-tile = blockIdx.y][chunk = blockIdx.x*2 + cw], 8192 elems.
    const size_t tbase = ((size_t)(n * 32 + blockIdx.y) * 64
                          + (size_t)(blockIdx.x * 2 + cw)) * 8192;
    __nv_bfloat16* ph = g_Phi + tbase;
    __nv_bfloat16* pl = g_Plo + tbase;
#pragma unroll
    for (int it = 0; it < 2; it++) {
        const int r80 = iw * 4 + it * 2;
#pragma unroll
        for (int jt = 0; jt < 8; jt++) {
            float e0 = __expf(d[it][jt][0]);
            float e1 = __expf(d[it][jt][1]);
            float e2 = __expf(d[it][jt][2]);
            float e3 = __expf(d[it][jt][3]);
            union { __nv_bfloat16 b[2]; uint32_t u; } h01, h23, l01, l23;
            h01.b[0] = __float2bfloat16(e0);
            h01.b[1] = __float2bfloat16(e1);
            h23.b[0] = __float2bfloat16(e2);
            h23.b[1] = __float2bfloat16(e3);
            l01.b[0] = __float2bfloat16(e0 - __bfloat162float(h01.b[0]));
            l01.b[1] = __float2bfloat16(e1 - __bfloat162float(h01.b[1]));
            l23.b[0] = __float2bfloat16(e2 - __bfloat162float(h23.b[0]));
            l23.b[1] = __float2bfloat16(e3 - __bfloat162float(h23.b[1]));
            const uint32_t off0 = ((uint32_t)(r80 * 8 + jt) * 8 + g) * 8 + 2 * tid;
            const uint32_t off1 = off0 + 512;   // r8 + 1
            *(uint32_t*)(ph + off0) = h01.u;
            *(uint32_t*)(ph + off1) = h23.u;
            *(uint32_t*)(pl + off0) = l01.u;
            *(uint32_t*)(pl + off1) = l23.u;
        }
    }
}

// ---------------------------------------------------------------------------
// K3: tensor-core PV GEMM via mma.sync + ldmatrix (bf16 hi/lo split),
// fused row-sum via all-ones B.  KT=64, double buffer (216KB smem),
// 512 thr / 16 warps, tile 128i x 256c.  Grid (32 i-tiles, 4 batches).
// P tiles are contiguous per stage: thread t loads chunk t (coalesced)
// and scatters to the smem location ldmatrix expects.
// ---------------------------------------------------------------------------
#define KT      64
#define NSTG    (NHW / KT)     // 64
#define ROWB    144            // 128B data + 16B pad -> conflict-free LDSM
#define A_HI    0
#define A_LO    18432          // 128*144
#define B_HI    36864
#define B_LO    73728          // 36864 + 256*144
#define STG     110592         // 73728 + 36864
#define K3_SMEM (2 * STG)      // 221184

__global__ __launch_bounds__(512, 1) void k3_mma(
    const float* __restrict__ a,
    const float* __restrict__ alphap,
    float* __restrict__ out)
{
    extern __shared__ __align__(16) char smc[];
    const uint32_t smb = (uint32_t)__cvta_generic_to_shared(smc);

    const int t    = threadIdx.x;
    const int lane = t & 31;
    const int warp = t >> 5;
    const int g    = lane >> 2;
    const int tid  = lane & 3;
    const int iw   = warp & 3;       // i-group (4 x 32)
    const int cw   = warp >> 2;      // c-group (4 x 64)
    const int n    = blockIdx.y;
    const int i0   = blockIdx.x * 128;

    // P tile base for this (n, i-tile); chunk s adds s*8192 elements.
    const size_t pbase = ((size_t)(n * 32 + blockIdx.x) * 64) * 8192;
    const __nv_bfloat16* Phi = g_Phi + pbase;
    const __nv_bfloat16* Plo = g_Plo + pbase;
    const __nv_bfloat16* Dhi = g_dhi + (size_t)n * CHN * NHW;
    const __nv_bfloat16* Dlo = g_dlo + (size_t)n * CHN * NHW;

    // A staging: thread t loads contiguous global chunk gidx = t + q*512,
    // stores to the smem slot holding (row = r8*8+rlow, col = jt).
    uint32_t aoff[2], agl[2], boff[4], bgl[4];
#pragma unroll
    for (int q = 0; q < 2; q++) {
        int gidx = t + q * 512;
        int r8   = gidx >> 6;
        int jt   = (gidx >> 3) & 7;
        int rlow = gidx & 7;
        aoff[q] = (uint32_t)((r8 * 8 + rlow) * ROWB + jt * 16);
        agl[q]  = (uint32_t)(gidx * 8);
    }
#pragma unroll
    for (int q = 0; q < 4; q++) {
        int idx = t + q * 512, row = idx >> 3, col = idx & 7;
        boff[q] = (uint32_t)(row * ROWB + col * 16);
        bgl[q]  = (uint32_t)(row * NHW + col * 8);
    }

    const uint32_t aAddr0 = (uint32_t)((iw * 32 + (lane & 15)) * ROWB + (lane >> 4) * 16);
    const uint32_t bAddrB = (uint32_t)((cw * 64 + (lane >> 4) * 8 + (lane & 7)) * ROWB
                                       + ((lane >> 3) & 1) * 16);

    float d[2][8][4];
#pragma unroll
    for (int it = 0; it < 2; it++)
#pragma unroll
        for (int ct = 0; ct < 8; ct++)
#pragma unroll
            for (int r = 0; r < 4; r++) d[it][ct][r] = 0.0f;

    float dsum[2][4];
#pragma unroll
    for (int it = 0; it < 2; it++)
#pragma unroll
        for (int r = 0; r < 4; r++) dsum[it][r] = 0.0f;
    const uint32_t ONES = 0x3F803F80u;

    // prologue: stage 0
    {
        const uint32_t bb = smb;
#pragma unroll
        for (int q = 0; q < 2; q++) cp_async16(bb + A_HI + aoff[q], Phi + agl[q]);
#pragma unroll
        for (int q = 0; q < 2; q++) cp_async16(bb + A_LO + aoff[q], Plo + agl[q]);
#pragma unroll
        for (int q = 0; q < 4; q++) cp_async16(bb + B_HI + boff[q], Dhi + bgl[q]);
#pragma unroll
        for (int q = 0; q < 4; q++) cp_async16(bb + B_LO + boff[q], Dlo + bgl[q]);
        CP_COMMIT();
    }

    for (int s = 0; s < NSTG; ++s) {
        if (s + 1 < NSTG) {
            __syncthreads();
            const uint32_t bb = smb + ((s + 1) & 1) * STG;
            const uint32_t pt = (uint32_t)(s + 1) * 8192;   // P tile chunk
            const uint32_t jt = (uint32_t)(s + 1) * KT;     // d^T column
#pragma unroll
            for (int q = 0; q < 2; q++) cp_async16(bb + A_HI + aoff[q], Phi + pt + agl[q]);
#pragma unroll
            for (int q = 0; q < 2; q++) cp_async16(bb + A_LO + aoff[q], Plo + pt + agl[q]);
#pragma unroll
            for (int q = 0; q < 4; q++) cp_async16(bb + B_HI + boff[q], Dhi + bgl[q] + jt);
#pragma unroll
            for (int q = 0; q < 4; q++) cp_async16(bb + B_LO + boff[q], Dlo + bgl[q] + jt);
            CP_COMMIT();
            CP_WAIT1();
        } else {
            CP_WAIT0();
        }
        __syncthreads();

        const uint32_t bufs = smb + (s & 1) * STG;

#pragma unroll
        for (int ks = 0; ks < 4; ks++) {
            const uint32_t kb = ks * 32;
            uint32_t ah[2][4], al[2][4];
#pragma unroll
            for (int it = 0; it < 2; it++) {
                const uint32_t aa = bufs + aAddr0 + it * (16 * ROWB) + kb;
                ldsm_x4(ah[it], aa + A_HI);
                ldsm_x4(al[it], aa + A_LO);
            }
            if (cw == 0) {   // fused row-sum: P(hi+lo) x ones
                mma_bf16(dsum[0], ah[0], ONES, ONES);
                mma_bf16(dsum[0], al[0], ONES, ONES);
                mma_bf16(dsum[1], ah[1], ONES, ONES);
                mma_bf16(dsum[1], al[1], ONES, ONES);
            }
#pragma unroll
            for (int ctp = 0; ctp < 4; ctp++) {
                const int ct0 = 2 * ctp;
                const uint32_t ba = bufs + bAddrB + ct0 * (8 * ROWB) + kb;
                uint32_t bh[4], bl[4];
                ldsm_x4(bh, ba + B_HI);
                ldsm_x4(bl, ba + B_LO);
                mma_bf16(d[0][ct0],     ah[0], bh[0], bh[1]);
                mma_bf16(d[1][ct0],     ah[1], bh[0], bh[1]);
                mma_bf16(d[0][ct0 + 1], ah[0], bh[2], bh[3]);
                mma_bf16(d[1][ct0 + 1], ah[1], bh[2], bh[3]);
                mma_bf16(d[0][ct0],     al[0], bh[0], bh[1]);
                mma_bf16(d[1][ct0],     al[1], bh[0], bh[1]);
                mma_bf16(d[0][ct0 + 1], al[0], bh[2], bh[3]);
                mma_bf16(d[1][ct0 + 1], al[1], bh[2], bh[3]);
                mma_bf16(d[0][ct0],     ah[0], bl[0], bl[1]);
                mma_bf16(d[1][ct0],     ah[1], bl[0], bl[1]);
                mma_bf16(d[0][ct0 + 1], ah[0], bl[2], bl[3]);
                mma_bf16(d[1][ct0 + 1], ah[1], bl[2], bl[3]);
            }
        }
    }
    __syncthreads();   // all compute done; smem free for epilogue

    // epilogue: row sums -> inv scale; ep[c][i] transpose; coalesced store
    float* ep    = (float*)smc;                 // [128][132]
    float* inv_s = (float*)(smc + 67584);       // [128]
    float* l_s   = (float*)(smc + 68096);       // [128]

    if (cw == 0 && tid == 0) {
        l_s[iw * 32 + g]          = dsum[0][0];
        l_s[iw * 32 + g + 8]      = dsum[0][2];
        l_s[iw * 32 + 16 + g]     = dsum[1][0];
        l_s[iw * 32 + 16 + g + 8] = dsum[1][2];
    }
    __syncthreads();
    if (t < 128) inv_s[t] = alphap[0] / l_s[t];

#pragma unroll
    for (int h = 0; h < 2; h++) {
        __syncthreads();
        if ((cw >> 1) == h) {
            const int cb = (cw & 1) * 64;
#pragma unroll
            for (int it = 0; it < 2; it++) {
                const int irow = iw * 32 + it * 16 + g;
#pragma unroll
                for (int ct = 0; ct < 8; ct++) {
                    const int crow = cb + ct * 8 + 2 * tid;
                    ep[crow * 132 + irow]           = d[it][ct][0];
                    ep[(crow + 1) * 132 + irow]     = d[it][ct][1];
                    ep[crow * 132 + irow + 8]       = d[it][ct][2];
                    ep[(crow + 1) * 132 + irow + 8] = d[it][ct][3];
                }
            }
        }
        __syncthreads();
        const int cl0 = t >> 5;
        const int i4  = (t & 31) * 4;
        const float4 iv = *(const float4*)&inv_s[i4];
#pragma unroll
        for (int p = 0; p < 8; p++) {
            const int cloc = cl0 + p * 16;
            float4 v = *(const float4*)&ep[cloc * 132 + i4];
            const size_t o = ((size_t)(n * CHN) + h * 128 + cloc) * NHW + i0 + i4;
            float4 av = *(const float4*)(a + o);
            *(float4*)(out + o) = make_float4(fmaf(iv.x, v.x, av.x),
                                              fmaf(iv.y, v.y, av.y),
                                              fmaf(iv.z, v.z, av.z),
                                              fmaf(iv.w, v.w, av.w));
        }
    }
}

// ---------------------------------------------------------------------------
extern "C" void kernel_launch(void* const* d_in, const int* in_sizes, int n_in,
                              void* d_out, int out_size)
{
    const float* a     = (const float*)d_in[0];
    const float* b_w   = (const float*)d_in[1];
    const float* b_b   = (const float*)d_in[2];
    const float* c_w   = (const float*)d_in[3];
    const float* c_b   = (const float*)d_in[4];
    const float* d_w   = (const float*)d_in[5];
    const float* d_b   = (const float*)d_in[6];
    const float* alpha = (const float*)d_in[7];
    float* out = (float*)d_out;

    cudaFuncSetAttribute(k3_mma, cudaFuncAttributeMaxDynamicSharedMemorySize, K3_SMEM);

    k1_conv<<<dim3(8, 20, 4), 256>>>(a, b_w, b_b, c_w, c_b, d_w, d_b);
    kd_split<<<dim3(128, 8, 4), 256>>>();
    k2_scores<<<dim3(32, 32, 4), 256>>>();
    k3_mma<<<dim3(32, 4), 512, K3_SMEM>>>(a, alpha, out);
}

// round 15
// speedup vs baseline: 1.0294x; 1.0294x over previous
#include <cuda_runtime.h>
#include <cuda_bf16.h>
#include <math.h>
#include <stdint.h>

#define NB   4
#define CHN  256
#define NHW  4096
#define MALL 320   // 32 (b) + 32 (c) + 256 (d)

// ---- scratch (device globals -- allocation is forbidden) ----
__device__ float         g_bcd[(size_t)NB * NHW * MALL];  // [n][i][320] (b,c used)
__device__ __nv_bfloat16 g_Phi[(size_t)NB * NHW * NHW];   // exp(s) hi (row-major)
__device__ __nv_bfloat16 g_Plo[(size_t)NB * NHW * NHW];   // exp(s) lo (row-major)
__device__ __nv_bfloat16 g_dhi[(size_t)NB * CHN * NHW];   // d^T hi  [n][c][j]
__device__ __nv_bfloat16 g_dlo[(size_t)NB * CHN * NHW];   // d^T lo

typedef unsigned long long ull;

__device__ __forceinline__ ull pack2(float lo, float hi) {
    ull r; asm("mov.b64 %0, {%1, %2};" : "=l"(r) : "f"(lo), "f"(hi)); return r;
}
__device__ __forceinline__ ull fma2(ull a, ull b, ull c) {
    ull d; asm("fma.rn.f32x2 %0, %1, %2, %3;" : "=l"(d) : "l"(a), "l"(b), "l"(c)); return d;
}
__device__ __forceinline__ float2 unpack2(ull v) {
    float2 f; asm("mov.b64 {%0, %1}, %2;" : "=f"(f.x), "=f"(f.y) : "l"(v)); return f;
}
__device__ __forceinline__ void cp_async16(uint32_t dst, const void* src) {
    asm volatile("cp.async.cg.shared.global [%0], [%1], 16;" :: "r"(dst), "l"(src));
}
#define CP_COMMIT() asm volatile("cp.async.commit_group;")
#define CP_WAIT0()  asm volatile("cp.async.wait_group 0;" ::: "memory")
#define CP_WAIT1()  asm volatile("cp.async.wait_group 1;" ::: "memory")

// warp-level bf16 tensor-core mma (baseline PTX, valid on sm_103 non-'a')
__device__ __forceinline__ void mma_bf16(float* d, const uint32_t* A,
                                         uint32_t b0, uint32_t b1) {
    asm volatile(
        "mma.sync.aligned.m16n8k16.row.col.f32.bf16.bf16.f32 "
        "{%0,%1,%2,%3}, {%4,%5,%6,%7}, {%8,%9}, {%0,%1,%2,%3};"
        : "+f"(d[0]), "+f"(d[1]), "+f"(d[2]), "+f"(d[3])
        : "r"(A[0]), "r"(A[1]), "r"(A[2]), "r"(A[3]), "r"(b0), "r"(b1));
}
__device__ __forceinline__ void ldsm_x4(uint32_t* r, uint32_t addr) {
    asm volatile("ldmatrix.sync.aligned.m8n8.x4.shared.b16 {%0,%1,%2,%3}, [%4];"
        : "=r"(r[0]), "=r"(r[1]), "=r"(r[2]), "=r"(r[3]) : "r"(addr));
}

// ---------------------------------------------------------------------------
// K1: fused 1x1 convs.  m-tile 16, 3 CTAs/SM.  Grid (8, 20, 4).
// Tiles with m0 >= 64 (the d channels) write bf16 hi/lo transposed d^T
// directly (replacing the old kd_split kernel); b,c tiles write g_bcd.
// ---------------------------------------------------------------------------
__global__ __launch_bounds__(256, 3) void k1_conv(
    const float* __restrict__ a,
    const float* __restrict__ b_w, const float* __restrict__ b_b,
    const float* __restrict__ c_w, const float* __restrict__ c_b,
    const float* __restrict__ d_w, const float* __restrict__ d_b)
{
    __shared__ float w_s[256][20];
    const int t  = threadIdx.x;
    const int n  = blockIdx.z;
    const int m0 = blockIdx.y * 16;
    const int i  = blockIdx.x * 512 + t;

#pragma unroll
    for (int k = 0; k < 16; k++) {
        int m = m0 + k;
        const float* wr = (m < 32) ? (b_w + m * 256)
                        : (m < 64) ? (c_w + (m - 32) * 256)
                                   : (d_w + (m - 64) * 256);
        w_s[t][k] = wr[t];
    }
    __syncthreads();

    ull acc[16];
#pragma unroll
    for (int q = 0; q < 8; q++) {
        int m = m0 + 2 * q;
        float bl = (m < 32) ? b_b[m] : (m < 64) ? c_b[m - 32] : d_b[m - 64];
        int m1 = m + 1;
        float bh = (m1 < 32) ? b_b[m1] : (m1 < 64) ? c_b[m1 - 32] : d_b[m1 - 64];
        acc[q] = pack2(bl, bh);
        acc[8 + q] = acc[q];
    }

    const float* ap = a + (size_t)n * CHN * NHW + i;
#pragma unroll 8
    for (int ch = 0; ch < 256; ch++) {
        float av0 = __ldg(ap + (size_t)ch * NHW);
        float av1 = __ldg(ap + (size_t)ch * NHW + 256);
        ull a20 = pack2(av0, av0);
        ull a21 = pack2(av1, av1);
        const ulonglong2* wrow = (const ulonglong2*)&w_s[ch][0];
#pragma unroll
        for (int q = 0; q < 4; q++) {
            ulonglong2 wv = wrow[q];
            acc[2 * q]         = fma2(a20, wv.x, acc[2 * q]);
            acc[2 * q + 1]     = fma2(a20, wv.y, acc[2 * q + 1]);
            acc[8 + 2 * q]     = fma2(a21, wv.x, acc[8 + 2 * q]);
            acc[8 + 2 * q + 1] = fma2(a21, wv.y, acc[8 + 2 * q + 1]);
        }
    }

    if (m0 < 64) {
        // b,c channels: fp32 rows into g_bcd
#pragma unroll
        for (int p = 0; p < 2; p++) {
            float* outp = g_bcd + ((size_t)n * NHW + i + p * 256) * MALL + m0;
#pragma unroll
            for (int q = 0; q < 4; q++) {
                float2 x = unpack2(acc[8 * p + 2 * q]);
                float2 y = unpack2(acc[8 * p + 2 * q + 1]);
                ((float4*)outp)[q] = make_float4(x.x, x.y, y.x, y.y);
            }
        }
    } else {
        // d channels: bf16 hi/lo split, transposed to [c][j]
        const int c0 = m0 - 64;
#pragma unroll
        for (int p = 0; p < 2; p++) {
            const size_t jb = (size_t)i + p * 256;
#pragma unroll
            for (int k = 0; k < 16; k++) {
                float2 x = unpack2(acc[8 * p + (k >> 1)]);
                float v = (k & 1) ? x.y : x.x;
                __nv_bfloat16 hi = __float2bfloat16(v);
                __nv_bfloat16 lo = __float2bfloat16(v - __bfloat162float(hi));
                size_t o = ((size_t)(n * CHN) + c0 + k) * NHW + jb;
                g_dhi[o] = hi;
                g_dlo[o] = lo;
            }
        }
    }
}

// ---------------------------------------------------------------------------
// K2: scores via tensor cores (bf16 hi/lo 3-split, K=32) + fused exp,
// direct bf16x2 stores of P hi/lo (row-major).  256 thr / 8 warps,
// tile 128i x 128j.  Grid (32 j-tiles, 32 i-tiles, 4 batches).
// ---------------------------------------------------------------------------
#define K2RB 80   // 64B data + 16B pad: LDSM conflict-free

__global__ __launch_bounds__(256) void k2_scores()
{
    __shared__ __align__(16) char sm2[4 * 128 * K2RB];   // 40960 B
    const uint32_t smb = (uint32_t)__cvta_generic_to_shared(sm2);
    const int AHI = 0, ALO = 10240, BHI = 20480, BLO = 30720;

    const int t    = threadIdx.x;
    const int lane = t & 31;
    const int warp = t >> 5;
    const int g    = lane >> 2;
    const int tid  = lane & 3;
    const int iw   = warp & 3;      // 4 i-groups of 32
    const int cw   = warp >> 2;     // 2 j-groups of 64
    const int n    = blockIdx.z;
    const int i0   = blockIdx.y * 128;
    const int j0   = blockIdx.x * 128;

    // ---- staging: 128 q rows + 128 c rows of 32 fp32 -> bf16 hi/lo ----
    {
        const int r  = t >> 1;
        const int hb = t & 1;
        const float* qs = g_bcd + ((size_t)(n * NHW) + i0 + r) * MALL + hb * 16;
        const float* cs = g_bcd + ((size_t)(n * NHW) + j0 + r) * MALL + 32 + hb * 16;
        const uint32_t dst = (uint32_t)(r * K2RB + hb * 32);
#pragma unroll
        for (int sel = 0; sel < 2; sel++) {
            const float* src = sel ? cs : qs;
            const int OH = sel ? BHI : AHI;
            const int OL = sel ? BLO : ALO;
#pragma unroll
            for (int q = 0; q < 2; q++) {
                float4 v0 = *(const float4*)(src + q * 8);
                float4 v1 = *(const float4*)(src + q * 8 + 4);
                float f[8] = {v0.x, v0.y, v0.z, v0.w, v1.x, v1.y, v1.z, v1.w};
                union { __nv_bfloat16 b[8]; uint4 u; } H, L;
#pragma unroll
                for (int k = 0; k < 8; k++) {
                    H.b[k] = __float2bfloat16(f[k]);
                    L.b[k] = __float2bfloat16(f[k] - __bfloat162float(H.b[k]));
                }
                *(uint4*)(sm2 + OH + dst + q * 16) = H.u;
                *(uint4*)(sm2 + OL + dst + q * 16) = L.u;
            }
        }
    }
    __syncthreads();

    // ---- MMA: S[128 x 128] = q . c^T (3-split bf16) ----
    const uint32_t aAddr = smb + (uint32_t)((iw * 32 + (lane & 15)) * K2RB + (lane >> 4) * 16);
    const uint32_t bAddr = smb + (uint32_t)((cw * 64 + (lane >> 4) * 8 + (lane & 7)) * K2RB
                                            + ((lane >> 3) & 1) * 16);
    float d[2][8][4];
#pragma unroll
    for (int it = 0; it < 2; it++)
#pragma unroll
        for (int jt = 0; jt < 8; jt++)
#pragma unroll
            for (int r = 0; r < 4; r++) d[it][jt][r] = 0.0f;

#pragma unroll
    for (int ks = 0; ks < 2; ks++) {
        const uint32_t kb = ks * 32;
        uint32_t ah[2][4], al[2][4];
#pragma unroll
        for (int it = 0; it < 2; it++) {
            const uint32_t aa = aAddr + it * (16 * K2RB) + kb;
            ldsm_x4(ah[it], aa + AHI);
            ldsm_x4(al[it], aa + ALO);
        }
#pragma unroll
        for (int ctp = 0; ctp < 4; ctp++) {
            const int ct0 = 2 * ctp;
            const uint32_t ba = bAddr + ct0 * (8 * K2RB) + kb;
            uint32_t bh[4], bl[4];
            ldsm_x4(bh, ba + BHI);
            ldsm_x4(bl, ba + BLO);
            mma_bf16(d[0][ct0],     ah[0], bh[0], bh[1]);
            mma_bf16(d[1][ct0],     ah[1], bh[0], bh[1]);
            mma_bf16(d[0][ct0 + 1], ah[0], bh[2], bh[3]);
            mma_bf16(d[1][ct0 + 1], ah[1], bh[2], bh[3]);
            mma_bf16(d[0][ct0],     al[0], bh[0], bh[1]);
            mma_bf16(d[1][ct0],     al[1], bh[0], bh[1]);
            mma_bf16(d[0][ct0 + 1], al[0], bh[2], bh[3]);
            mma_bf16(d[1][ct0 + 1], al[1], bh[2], bh[3]);
            mma_bf16(d[0][ct0],     ah[0], bl[0], bl[1]);
            mma_bf16(d[1][ct0],     ah[1], bl[0], bl[1]);
            mma_bf16(d[0][ct0 + 1], ah[0], bl[2], bl[3]);
            mma_bf16(d[1][ct0 + 1], ah[1], bl[2], bl[3]);
        }
    }

    // ---- epilogue: exp + hi/lo split + direct bf16x2 stores ----
#pragma unroll
    for (int it = 0; it < 2; it++) {
        const size_t rb0 = ((size_t)(n * NHW) + i0 + iw * 32 + it * 16 + g) * NHW;
        const size_t rb1 = rb0 + (size_t)8 * NHW;
#pragma unroll
        for (int jt = 0; jt < 8; jt++) {
            const int col = j0 + cw * 64 + jt * 8 + 2 * tid;
            float e0 = __expf(d[it][jt][0]);
            float e1 = __expf(d[it][jt][1]);
            float e2 = __expf(d[it][jt][2]);
            float e3 = __expf(d[it][jt][3]);
            union { __nv_bfloat16 b[2]; uint32_t u; } h01, h23, l01, l23;
            h01.b[0] = __float2bfloat16(e0);
            h01.b[1] = __float2bfloat16(e1);
            h23.b[0] = __float2bfloat16(e2);
            h23.b[1] = __float2bfloat16(e3);
            l01.b[0] = __float2bfloat16(e0 - __bfloat162float(h01.b[0]));
            l01.b[1] = __float2bfloat16(e1 - __bfloat162float(h01.b[1]));
            l23.b[0] = __float2bfloat16(e2 - __bfloat162float(h23.b[0]));
            l23.b[1] = __float2bfloat16(e3 - __bfloat162float(h23.b[1]));
            *(uint32_t*)(g_Phi + rb0 + col) = h01.u;
            *(uint32_t*)(g_Phi + rb1 + col) = h23.u;
            *(uint32_t*)(g_Plo + rb0 + col) = l01.u;
            *(uint32_t*)(g_Plo + rb1 + col) = l23.u;
        }
    }
}

// ---------------------------------------------------------------------------
// K3: tensor-core PV GEMM via mma.sync + ldmatrix (bf16 hi/lo split),
// fused row-sum via all-ones B.  KT=64, double buffer (216KB smem),
// 512 thr / 16 warps, tile 128i x 256c.  Grid (32 i-tiles, 4 batches).
// Row-major P staging (proven round-10 configuration).
// ---------------------------------------------------------------------------
#define KT      64
#define NSTG    (NHW / KT)     // 64
#define ROWB    144            // 128B data + 16B pad -> conflict-free LDSM
#define A_HI    0
#define A_LO    18432          // 128*144
#define B_HI    36864
#define B_LO    73728          // 36864 + 256*144
#define STG     110592         // 73728 + 36864
#define K3_SMEM (2 * STG)      // 221184

__global__ __launch_bounds__(512, 1) void k3_mma(
    const float* __restrict__ a,
    const float* __restrict__ alphap,
    float* __restrict__ out)
{
    extern __shared__ __align__(16) char smc[];
    const uint32_t smb = (uint32_t)__cvta_generic_to_shared(smc);

    const int t    = threadIdx.x;
    const int lane = t & 31;
    const int warp = t >> 5;
    const int g    = lane >> 2;
    const int tid  = lane & 3;
    const int iw   = warp & 3;       // i-group (4 x 32)
    const int cw   = warp >> 2;      // c-group (4 x 64)
    const int n    = blockIdx.y;
    const int i0   = blockIdx.x * 128;

    const __nv_bfloat16* Phi = g_Phi + (size_t)(n * NHW + i0) * NHW;
    const __nv_bfloat16* Plo = g_Plo + (size_t)(n * NHW + i0) * NHW;
    const __nv_bfloat16* Dhi = g_dhi + (size_t)n * CHN * NHW;
    const __nv_bfloat16* Dlo = g_dlo + (size_t)n * CHN * NHW;

    // staging coords (16B chunks, 8 per 128B row)
    uint32_t aoff[2], agl[2], boff[4], bgl[4];
#pragma unroll
    for (int q = 0; q < 2; q++) {
        int idx = t + q * 512, row = idx >> 3, col = idx & 7;
        aoff[q] = (uint32_t)(row * ROWB + col * 16);
        agl[q]  = (uint32_t)(row * NHW + col * 8);
    }
#pragma unroll
    for (int q = 0; q < 4; q++) {
        int idx = t + q * 512, row = idx >> 3, col = idx & 7;
        boff[q] = (uint32_t)(row * ROWB + col * 16);
        bgl[q]  = (uint32_t)(row * NHW + col * 8);
    }

    const uint32_t aAddr0 = (uint32_t)((iw * 32 + (lane & 15)) * ROWB + (lane >> 4) * 16);
    const uint32_t bAddrB = (uint32_t)((cw * 64 + (lane >> 4) * 8 + (lane & 7)) * ROWB
                                       + ((lane >> 3) & 1) * 16);

    float d[2][8][4];
#pragma unroll
    for (int it = 0; it < 2; it++)
#pragma unroll
        for (int ct = 0; ct < 8; ct++)
#pragma unroll
            for (int r = 0; r < 4; r++) d[it][ct][r] = 0.0f;

    float dsum[2][4];
#pragma unroll
    for (int it = 0; it < 2; it++)
#pragma unroll
        for (int r = 0; r < 4; r++) dsum[it][r] = 0.0f;
    const uint32_t ONES = 0x3F803F80u;

    // prologue: stage 0
    {
        const uint32_t bb = smb;
#pragma unroll
        for (int q = 0; q < 2; q++) cp_async16(bb + A_HI + aoff[q], Phi + agl[q]);
#pragma unroll
        for (int q = 0; q < 2; q++) cp_async16(bb + A_LO + aoff[q], Plo + agl[q]);
#pragma unroll
        for (int q = 0; q < 4; q++) cp_async16(bb + B_HI + boff[q], Dhi + bgl[q]);
#pragma unroll
        for (int q = 0; q < 4; q++) cp_async16(bb + B_LO + boff[q], Dlo + bgl[q]);
        CP_COMMIT();
    }

    for (int s = 0; s < NSTG; ++s) {
        if (s + 1 < NSTG) {
            __syncthreads();
            const uint32_t bb = smb + ((s + 1) & 1) * STG;
            const uint32_t jt = (uint32_t)(s + 1) * KT;
#pragma unroll
            for (int q = 0; q < 2; q++) cp_async16(bb + A_HI + aoff[q], Phi + agl[q] + jt);
#pragma unroll
            for (int q = 0; q < 2; q++) cp_async16(bb + A_LO + aoff[q], Plo + agl[q] + jt);
#pragma unroll
            for (int q = 0; q < 4; q++) cp_async16(bb + B_HI + boff[q], Dhi + bgl[q] + jt);
#pragma unroll
            for (int q = 0; q < 4; q++) cp_async16(bb + B_LO + boff[q], Dlo + bgl[q] + jt);
            CP_COMMIT();
            CP_WAIT1();
        } else {
            CP_WAIT0();
        }
        __syncthreads();

        const uint32_t bufs = smb + (s & 1) * STG;

#pragma unroll
        for (int ks = 0; ks < 4; ks++) {
            const uint32_t kb = ks * 32;
            uint32_t ah[2][4], al[2][4];
#pragma unroll
            for (int it = 0; it < 2; it++) {
                const uint32_t aa = bufs + aAddr0 + it * (16 * ROWB) + kb;
                ldsm_x4(ah[it], aa + A_HI);
                ldsm_x4(al[it], aa + A_LO);
            }
            if (cw == 0) {   // fused row-sum: P(hi+lo) x ones
                mma_bf16(dsum[0], ah[0], ONES, ONES);
                mma_bf16(dsum[0], al[0], ONES, ONES);
                mma_bf16(dsum[1], ah[1], ONES, ONES);
                mma_bf16(dsum[1], al[1], ONES, ONES);
            }
#pragma unroll
            for (int ctp = 0; ctp < 4; ctp++) {
                const int ct0 = 2 * ctp;
                const uint32_t ba = bufs + bAddrB + ct0 * (8 * ROWB) + kb;
                uint32_t bh[4], bl[4];
                ldsm_x4(bh, ba + B_HI);
                ldsm_x4(bl, ba + B_LO);
                mma_bf16(d[0][ct0],     ah[0], bh[0], bh[1]);
                mma_bf16(d[1][ct0],     ah[1], bh[0], bh[1]);
                mma_bf16(d[0][ct0 + 1], ah[0], bh[2], bh[3]);
                mma_bf16(d[1][ct0 + 1], ah[1], bh[2], bh[3]);
                mma_bf16(d[0][ct0],     al[0], bh[0], bh[1]);
                mma_bf16(d[1][ct0],     al[1], bh[0], bh[1]);
                mma_bf16(d[0][ct0 + 1], al[0], bh[2], bh[3]);
                mma_bf16(d[1][ct0 + 1], al[1], bh[2], bh[3]);
                mma_bf16(d[0][ct0],     ah[0], bl[0], bl[1]);
                mma_bf16(d[1][ct0],     ah[1], bl[0], bl[1]);
                mma_bf16(d[0][ct0 + 1], ah[0], bl[2], bl[3]);
                mma_bf16(d[1][ct0 + 1], ah[1], bl[2], bl[3]);
            }
        }
    }
    __syncthreads();   // all compute done; smem free for epilogue

    // epilogue: row sums -> inv scale; ep[c][i] transpose; coalesced store
    float* ep    = (float*)smc;                 // [128][132]
    float* inv_s = (float*)(smc + 67584);       // [128]
    float* l_s   = (float*)(smc + 68096);       // [128]

    if (cw == 0 && tid == 0) {
        l_s[iw * 32 + g]          = dsum[0][0];
        l_s[iw * 32 + g + 8]      = dsum[0][2];
        l_s[iw * 32 + 16 + g]     = dsum[1][0];
        l_s[iw * 32 + 16 + g + 8] = dsum[1][2];
    }
    __syncthreads();
    if (t < 128) inv_s[t] = alphap[0] / l_s[t];

#pragma unroll
    for (int h = 0; h < 2; h++) {
        __syncthreads();
        if ((cw >> 1) == h) {
            const int cb = (cw & 1) * 64;
#pragma unroll
            for (int it = 0; it < 2; it++) {
                const int irow = iw * 32 + it * 16 + g;
#pragma unroll
                for (int ct = 0; ct < 8; ct++) {
                    const int crow = cb + ct * 8 + 2 * tid;
                    ep[crow * 132 + irow]           = d[it][ct][0];
                    ep[(crow + 1) * 132 + irow]     = d[it][ct][1];
                    ep[crow * 132 + irow + 8]       = d[it][ct][2];
                    ep[(crow + 1) * 132 + irow + 8] = d[it][ct][3];
                }
            }
        }
        __syncthreads();
        const int cl0 = t >> 5;
        const int i4  = (t & 31) * 4;
        const float4 iv = *(const float4*)&inv_s[i4];
#pragma unroll
        for (int p = 0; p < 8; p++) {
            const int cloc = cl0 + p * 16;
            float4 v = *(const float4*)&ep[cloc * 132 + i4];
            const size_t o = ((size_t)(n * CHN) + h * 128 + cloc) * NHW + i0 + i4;
            float4 av = *(const float4*)(a + o);
            *(float4*)(out + o) = make_float4(fmaf(iv.x, v.x, av.x),
                                              fmaf(iv.y, v.y, av.y),
                                              fmaf(iv.z, v.z, av.z),
                                              fmaf(iv.w, v.w, av.w));
        }
    }
}

// ---------------------------------------------------------------------------
extern "C" void kernel_launch(void* const* d_in, const int* in_sizes, int n_in,
                              void* d_out, int out_size)
{
    const float* a     = (const float*)d_in[0];
    const float* b_w   = (const float*)d_in[1];
    const float* b_b   = (const float*)d_in[2];
    const float* c_w   = (const float*)d_in[3];
    const float* c_b   = (const float*)d_in[4];
    const float* d_w   = (const float*)d_in[5];
    const float* d_b   = (const float*)d_in[6];
    const float* alpha = (const float*)d_in[7];
    float* out = (float*)d_out;

    cudaFuncSetAttribute(k3_mma, cudaFuncAttributeMaxDynamicSharedMemorySize, K3_SMEM);

    k1_conv<<<dim3(8, 20, 4), 256>>>(a, b_w, b_b, c_w, c_b, d_w, d_b);
    k2_scores<<<dim3(32, 32, 4), 256>>>();
    k3_mma<<<dim3(32, 4), 512, K3_SMEM>>>(a, alpha, out);
}

// round 16
// speedup vs baseline: 1.0520x; 1.0220x over previous
#include <cuda_runtime.h>
#include <cuda_bf16.h>
#include <math.h>
#include <stdint.h>

#define NB   4
#define CHN  256
#define NHW  4096
#define MALL 320   // 32 (b) + 32 (c) + 256 (d)

// ---- scratch (device globals -- allocation is forbidden) ----
__device__ float         g_bcd[(size_t)NB * NHW * MALL];  // [n][i][320] (b,c used)
__device__ __nv_bfloat16 g_Phi[(size_t)NB * NHW * NHW];   // exp(s) hi (row-major)
__device__ __nv_bfloat16 g_Plo[(size_t)NB * NHW * NHW];   // exp(s) lo (row-major)
__device__ __nv_bfloat16 g_dhi[(size_t)NB * CHN * NHW];   // d^T hi  [n][c][j]
__device__ __nv_bfloat16 g_dlo[(size_t)NB * CHN * NHW];   // d^T lo

typedef unsigned long long ull;

__device__ __forceinline__ ull pack2(float lo, float hi) {
    ull r; asm("mov.b64 %0, {%1, %2};" : "=l"(r) : "f"(lo), "f"(hi)); return r;
}
__device__ __forceinline__ ull fma2(ull a, ull b, ull c) {
    ull d; asm("fma.rn.f32x2 %0, %1, %2, %3;" : "=l"(d) : "l"(a), "l"(b), "l"(c)); return d;
}
__device__ __forceinline__ float2 unpack2(ull v) {
    float2 f; asm("mov.b64 {%0, %1}, %2;" : "=f"(f.x), "=f"(f.y) : "l"(v)); return f;
}
__device__ __forceinline__ void cp_async16(uint32_t dst, const void* src) {
    asm volatile("cp.async.cg.shared.global [%0], [%1], 16;" :: "r"(dst), "l"(src));
}
#define CP_COMMIT() asm volatile("cp.async.commit_group;")
#define CP_WAIT0()  asm volatile("cp.async.wait_group 0;" ::: "memory")
#define CP_WAIT1()  asm volatile("cp.async.wait_group 1;" ::: "memory")

// warp-level bf16 tensor-core mma (baseline PTX, valid on sm_103 non-'a')
__device__ __forceinline__ void mma_bf16(float* d, const uint32_t* A,
                                         uint32_t b0, uint32_t b1) {
    asm volatile(
        "mma.sync.aligned.m16n8k16.row.col.f32.bf16.bf16.f32 "
        "{%0,%1,%2,%3}, {%4,%5,%6,%7}, {%8,%9}, {%0,%1,%2,%3};"
        : "+f"(d[0]), "+f"(d[1]), "+f"(d[2]), "+f"(d[3])
        : "r"(A[0]), "r"(A[1]), "r"(A[2]), "r"(A[3]), "r"(b0), "r"(b1));
}
__device__ __forceinline__ void ldsm_x4(uint32_t* r, uint32_t addr) {
    asm volatile("ldmatrix.sync.aligned.m8n8.x4.shared.b16 {%0,%1,%2,%3}, [%4];"
        : "=r"(r[0]), "=r"(r[1]), "=r"(r[2]), "=r"(r[3]) : "r"(addr));
}

// ---------------------------------------------------------------------------
// K1: fused 1x1 convs.  m-tile 16, 3 CTAs/SM.  Grid (8, 20, 4).
// Tiles with m0 >= 64 (the d channels) write bf16 hi/lo transposed d^T
// directly; b,c tiles write g_bcd.
// ---------------------------------------------------------------------------
__global__ __launch_bounds__(256, 3) void k1_conv(
    const float* __restrict__ a,
    const float* __restrict__ b_w, const float* __restrict__ b_b,
    const float* __restrict__ c_w, const float* __restrict__ c_b,
    const float* __restrict__ d_w, const float* __restrict__ d_b)
{
    __shared__ float w_s[256][20];
    const int t  = threadIdx.x;
    const int n  = blockIdx.z;
    const int m0 = blockIdx.y * 16;
    const int i  = blockIdx.x * 512 + t;

#pragma unroll
    for (int k = 0; k < 16; k++) {
        int m = m0 + k;
        const float* wr = (m < 32) ? (b_w + m * 256)
                        : (m < 64) ? (c_w + (m - 32) * 256)
                                   : (d_w + (m - 64) * 256);
        w_s[t][k] = wr[t];
    }
    __syncthreads();

    ull acc[16];
#pragma unroll
    for (int q = 0; q < 8; q++) {
        int m = m0 + 2 * q;
        float bl = (m < 32) ? b_b[m] : (m < 64) ? c_b[m - 32] : d_b[m - 64];
        int m1 = m + 1;
        float bh = (m1 < 32) ? b_b[m1] : (m1 < 64) ? c_b[m1 - 32] : d_b[m1 - 64];
        acc[q] = pack2(bl, bh);
        acc[8 + q] = acc[q];
    }

    const float* ap = a + (size_t)n * CHN * NHW + i;
#pragma unroll 8
    for (int ch = 0; ch < 256; ch++) {
        float av0 = __ldg(ap + (size_t)ch * NHW);
        float av1 = __ldg(ap + (size_t)ch * NHW + 256);
        ull a20 = pack2(av0, av0);
        ull a21 = pack2(av1, av1);
        const ulonglong2* wrow = (const ulonglong2*)&w_s[ch][0];
#pragma unroll
        for (int q = 0; q < 4; q++) {
            ulonglong2 wv = wrow[q];
            acc[2 * q]         = fma2(a20, wv.x, acc[2 * q]);
            acc[2 * q + 1]     = fma2(a20, wv.y, acc[2 * q + 1]);
            acc[8 + 2 * q]     = fma2(a21, wv.x, acc[8 + 2 * q]);
            acc[8 + 2 * q + 1] = fma2(a21, wv.y, acc[8 + 2 * q + 1]);
        }
    }

    if (m0 < 64) {
#pragma unroll
        for (int p = 0; p < 2; p++) {
            float* outp = g_bcd + ((size_t)n * NHW + i + p * 256) * MALL + m0;
#pragma unroll
            for (int q = 0; q < 4; q++) {
                float2 x = unpack2(acc[8 * p + 2 * q]);
                float2 y = unpack2(acc[8 * p + 2 * q + 1]);
                ((float4*)outp)[q] = make_float4(x.x, x.y, y.x, y.y);
            }
        }
    } else {
        const int c0 = m0 - 64;
#pragma unroll
        for (int p = 0; p < 2; p++) {
            const size_t jb = (size_t)i + p * 256;
#pragma unroll
            for (int k = 0; k < 16; k++) {
                float2 x = unpack2(acc[8 * p + (k >> 1)]);
                float v = (k & 1) ? x.y : x.x;
                __nv_bfloat16 hi = __float2bfloat16(v);
                __nv_bfloat16 lo = __float2bfloat16(v - __bfloat162float(hi));
                size_t o = ((size_t)(n * CHN) + c0 + k) * NHW + jb;
                g_dhi[o] = hi;
                g_dlo[o] = lo;
            }
        }
    }
}

// ---------------------------------------------------------------------------
// K2: scores via tensor cores (bf16 hi/lo 3-split, K=32) + fused exp.
// Epilogue: per-warp smem transpose -> 16B/lane stores, full 32B sectors.
// 256 thr / 8 warps, tile 128i x 128j.  Grid (32 j-tiles, 32 i-tiles, 4).
// ---------------------------------------------------------------------------
#define K2RB 80    // 64B data + 16B pad: LDSM conflict-free
#define WROW 144   // per-warp epilogue row stride (16-aligned; CF writes)

__global__ __launch_bounds__(256) void k2_scores()
{
    __shared__ __align__(16) char sm2[4 * 128 * K2RB];   // 40960 B
    const uint32_t smb = (uint32_t)__cvta_generic_to_shared(sm2);
    const int AHI = 0, ALO = 10240, BHI = 20480, BLO = 30720;

    const int t    = threadIdx.x;
    const int lane = t & 31;
    const int warp = t >> 5;
    const int g    = lane >> 2;
    const int tid  = lane & 3;
    const int iw   = warp & 3;      // 4 i-groups of 32
    const int cw   = warp >> 2;     // 2 j-groups of 64
    const int n    = blockIdx.z;
    const int i0   = blockIdx.y * 128;
    const int j0   = blockIdx.x * 128;

    // ---- staging: 128 q rows + 128 c rows of 32 fp32 -> bf16 hi/lo ----
    {
        const int r  = t >> 1;
        const int hb = t & 1;
        const float* qs = g_bcd + ((size_t)(n * NHW) + i0 + r) * MALL + hb * 16;
        const float* cs = g_bcd + ((size_t)(n * NHW) + j0 + r) * MALL + 32 + hb * 16;
        const uint32_t dst = (uint32_t)(r * K2RB + hb * 32);
#pragma unroll
        for (int sel = 0; sel < 2; sel++) {
            const float* src = sel ? cs : qs;
            const int OH = sel ? BHI : AHI;
            const int OL = sel ? BLO : ALO;
#pragma unroll
            for (int q = 0; q < 2; q++) {
                float4 v0 = *(const float4*)(src + q * 8);
                float4 v1 = *(const float4*)(src + q * 8 + 4);
                float f[8] = {v0.x, v0.y, v0.z, v0.w, v1.x, v1.y, v1.z, v1.w};
                union { __nv_bfloat16 b[8]; uint4 u; } H, L;
#pragma unroll
                for (int k = 0; k < 8; k++) {
                    H.b[k] = __float2bfloat16(f[k]);
                    L.b[k] = __float2bfloat16(f[k] - __bfloat162float(H.b[k]));
                }
                *(uint4*)(sm2 + OH + dst + q * 16) = H.u;
                *(uint4*)(sm2 + OL + dst + q * 16) = L.u;
            }
        }
    }
    __syncthreads();

    // ---- MMA: S[128 x 128] = q . c^T (3-split bf16) ----
    const uint32_t aAddr = smb + (uint32_t)((iw * 32 + (lane & 15)) * K2RB + (lane >> 4) * 16);
    const uint32_t bAddr = smb + (uint32_t)((cw * 64 + (lane >> 4) * 8 + (lane & 7)) * K2RB
                                            + ((lane >> 3) & 1) * 16);
    float d[2][8][4];
#pragma unroll
    for (int it = 0; it < 2; it++)
#pragma unroll
        for (int jt = 0; jt < 8; jt++)
#pragma unroll
            for (int r = 0; r < 4; r++) d[it][jt][r] = 0.0f;

#pragma unroll
    for (int ks = 0; ks < 2; ks++) {
        const uint32_t kb = ks * 32;
        uint32_t ah[2][4], al[2][4];
#pragma unroll
        for (int it = 0; it < 2; it++) {
            const uint32_t aa = aAddr + it * (16 * K2RB) + kb;
            ldsm_x4(ah[it], aa + AHI);
            ldsm_x4(al[it], aa + ALO);
        }
#pragma unroll
        for (int ctp = 0; ctp < 4; ctp++) {
            const int ct0 = 2 * ctp;
            const uint32_t ba = bAddr + ct0 * (8 * K2RB) + kb;
            uint32_t bh[4], bl[4];
            ldsm_x4(bh, ba + BHI);
            ldsm_x4(bl, ba + BLO);
            mma_bf16(d[0][ct0],     ah[0], bh[0], bh[1]);
            mma_bf16(d[1][ct0],     ah[1], bh[0], bh[1]);
            mma_bf16(d[0][ct0 + 1], ah[0], bh[2], bh[3]);
            mma_bf16(d[1][ct0 + 1], ah[1], bh[2], bh[3]);
            mma_bf16(d[0][ct0],     al[0], bh[0], bh[1]);
            mma_bf16(d[1][ct0],     al[1], bh[0], bh[1]);
            mma_bf16(d[0][ct0 + 1], al[0], bh[2], bh[3]);
            mma_bf16(d[1][ct0 + 1], al[1], bh[2], bh[3]);
            mma_bf16(d[0][ct0],     ah[0], bl[0], bl[1]);
            mma_bf16(d[1][ct0],     ah[1], bl[0], bl[1]);
            mma_bf16(d[0][ct0 + 1], ah[0], bl[2], bl[3]);
            mma_bf16(d[1][ct0 + 1], ah[1], bl[2], bl[3]);
        }
    }
    __syncthreads();   // all ldmatrix reads of staging done; reuse smem per-warp

    // ---- epilogue: exp + hi/lo split; per-warp smem transpose; 16B stores ----
    // Warp-private strip: 16 rows x WROW bytes (64 bf16 data + pad).
    char* ws = sm2 + warp * (16 * WROW);
    const int rrow = lane >> 1;               // read row 0..15
    const int rch  = lane & 1;                // read chunk parity
    const size_t gi = (size_t)(n * NHW) + i0 + iw * 32;   // + it*16 + rrow
    const int    gj = j0 + cw * 64;

#pragma unroll
    for (int it = 0; it < 2; it++) {
        // exp + pack fragments for this it
        uint32_t vh[2][8], vl[2][8];          // [rs(row g / g+8)][jt]
#pragma unroll
        for (int jt = 0; jt < 8; jt++) {
            float e0 = __expf(d[it][jt][0]);
            float e1 = __expf(d[it][jt][1]);
            float e2 = __expf(d[it][jt][2]);
            float e3 = __expf(d[it][jt][3]);
            union { __nv_bfloat16 b[2]; uint32_t u; } p;
            __nv_bfloat16 h0 = __float2bfloat16(e0);
            __nv_bfloat16 h1 = __float2bfloat16(e1);
            __nv_bfloat16 h2 = __float2bfloat16(e2);
            __nv_bfloat16 h3 = __float2bfloat16(e3);
            p.b[0] = h0; p.b[1] = h1; vh[0][jt] = p.u;
            p.b[0] = h2; p.b[1] = h3; vh[1][jt] = p.u;
            p.b[0] = __float2bfloat16(e0 - __bfloat162float(h0));
            p.b[1] = __float2bfloat16(e1 - __bfloat162float(h1));
            vl[0][jt] = p.u;
            p.b[0] = __float2bfloat16(e2 - __bfloat162float(h2));
            p.b[1] = __float2bfloat16(e3 - __bfloat162float(h3));
            vl[1][jt] = p.u;
        }
#pragma unroll
        for (int hl = 0; hl < 2; hl++) {      // 0 = hi, 1 = lo
            // scatter into warp strip (conflict-free: banks 4g+4jt+tid)
#pragma unroll
            for (int rs = 0; rs < 2; rs++) {
                const int row = g + 8 * rs;
#pragma unroll
                for (int jt = 0; jt < 8; jt++) {
                    uint32_t v = hl ? vl[rs][jt] : vh[rs][jt];
                    *(uint32_t*)(ws + row * WROW + jt * 16 + tid * 4) = v;
                }
            }
            __syncwarp();
            // coalesced re-emit: 16B per lane, lane pairs = full 32B sectors
            __nv_bfloat16* gdst = hl ? g_Plo : g_Phi;
#pragma unroll
            for (int pass = 0; pass < 4; pass++) {
                const int ch = pass * 2 + rch;
                uint4 v = *(const uint4*)(ws + rrow * WROW + ch * 16);
                *(uint4*)(gdst + (gi + it * 16 + rrow) * NHW + gj + ch * 8) = v;
            }
            __syncwarp();
        }
    }
}

// ---------------------------------------------------------------------------
// K3: tensor-core PV GEMM via mma.sync + ldmatrix (bf16 hi/lo split),
// fused row-sum via all-ones B.  KT=64, double buffer (216KB smem),
// 512 thr / 16 warps, tile 128i x 256c.  Grid (32 i-tiles, 4 batches).
// ---------------------------------------------------------------------------
#define KT      64
#define NSTG    (NHW / KT)     // 64
#define ROWB    144            // 128B data + 16B pad -> conflict-free LDSM
#define A_HI    0
#define A_LO    18432          // 128*144
#define B_HI    36864
#define B_LO    73728          // 36864 + 256*144
#define STG     110592         // 73728 + 36864
#define K3_SMEM (2 * STG)      // 221184

__global__ __launch_bounds__(512, 1) void k3_mma(
    const float* __restrict__ a,
    const float* __restrict__ alphap,
    float* __restrict__ out)
{
    extern __shared__ __align__(16) char smc[];
    const uint32_t smb = (uint32_t)__cvta_generic_to_shared(smc);

    const int t    = threadIdx.x;
    const int lane = t & 31;
    const int warp = t >> 5;
    const int g    = lane >> 2;
    const int tid  = lane & 3;
    const int iw   = warp & 3;       // i-group (4 x 32)
    const int cw   = warp >> 2;      // c-group (4 x 64)
    const int n    = blockIdx.y;
    const int i0   = blockIdx.x * 128;

    const __nv_bfloat16* Phi = g_Phi + (size_t)(n * NHW + i0) * NHW;
    const __nv_bfloat16* Plo = g_Plo + (size_t)(n * NHW + i0) * NHW;
    const __nv_bfloat16* Dhi = g_dhi + (size_t)n * CHN * NHW;
    const __nv_bfloat16* Dlo = g_dlo + (size_t)n * CHN * NHW;

    uint32_t aoff[2], agl[2], boff[4], bgl[4];
#pragma unroll
    for (int q = 0; q < 2; q++) {
        int idx = t + q * 512, row = idx >> 3, col = idx & 7;
        aoff[q] = (uint32_t)(row * ROWB + col * 16);
        agl[q]  = (uint32_t)(row * NHW + col * 8);
    }
#pragma unroll
    for (int q = 0; q < 4; q++) {
        int idx = t + q * 512, row = idx >> 3, col = idx & 7;
        boff[q] = (uint32_t)(row * ROWB + col * 16);
        bgl[q]  = (uint32_t)(row * NHW + col * 8);
    }

    const uint32_t aAddr0 = (uint32_t)((iw * 32 + (lane & 15)) * ROWB + (lane >> 4) * 16);
    const uint32_t bAddrB = (uint32_t)((cw * 64 + (lane >> 4) * 8 + (lane & 7)) * ROWB
                                       + ((lane >> 3) & 1) * 16);

    float d[2][8][4];
#pragma unroll
    for (int it = 0; it < 2; it++)
#pragma unroll
        for (int ct = 0; ct < 8; ct++)
#pragma unroll
            for (int r = 0; r < 4; r++) d[it][ct][r] = 0.0f;

    float dsum[2][4];
#pragma unroll
    for (int it = 0; it < 2; it++)
#pragma unroll
        for (int r = 0; r < 4; r++) dsum[it][r] = 0.0f;
    const uint32_t ONES = 0x3F803F80u;

    {
        const uint32_t bb = smb;
#pragma unroll
        for (int q = 0; q < 2; q++) cp_async16(bb + A_HI + aoff[q], Phi + agl[q]);
#pragma unroll
        for (int q = 0; q < 2; q++) cp_async16(bb + A_LO + aoff[q], Plo + agl[q]);
#pragma unroll
        for (int q = 0; q < 4; q++) cp_async16(bb + B_HI + boff[q], Dhi + bgl[q]);
#pragma unroll
        for (int q = 0; q < 4; q++) cp_async16(bb + B_LO + boff[q], Dlo + bgl[q]);
        CP_COMMIT();
    }

    for (int s = 0; s < NSTG; ++s) {
        if (s + 1 < NSTG) {
            __syncthreads();
            const uint32_t bb = smb + ((s + 1) & 1) * STG;
            const uint32_t jt = (uint32_t)(s + 1) * KT;
#pragma unroll
            for (int q = 0; q < 2; q++) cp_async16(bb + A_HI + aoff[q], Phi + agl[q] + jt);
#pragma unroll
            for (int q = 0; q < 2; q++) cp_async16(bb + A_LO + aoff[q], Plo + agl[q] + jt);
#pragma unroll
            for (int q = 0; q < 4; q++) cp_async16(bb + B_HI + boff[q], Dhi + bgl[q] + jt);
#pragma unroll
            for (int q = 0; q < 4; q++) cp_async16(bb + B_LO + boff[q], Dlo + bgl[q] + jt);
            CP_COMMIT();
            CP_WAIT1();
        } else {
            CP_WAIT0();
        }
        __syncthreads();

        const uint32_t bufs = smb + (s & 1) * STG;

#pragma unroll
        for (int ks = 0; ks < 4; ks++) {
            const uint32_t kb = ks * 32;
            uint32_t ah[2][4], al[2][4];
#pragma unroll
            for (int it = 0; it < 2; it++) {
                const uint32_t aa = bufs + aAddr0 + it * (16 * ROWB) + kb;
                ldsm_x4(ah[it], aa + A_HI);
                ldsm_x4(al[it], aa + A_LO);
            }
            if (cw == 0) {
                mma_bf16(dsum[0], ah[0], ONES, ONES);
                mma_bf16(dsum[0], al[0], ONES, ONES);
                mma_bf16(dsum[1], ah[1], ONES, ONES);
                mma_bf16(dsum[1], al[1], ONES, ONES);
            }
#pragma unroll
            for (int ctp = 0; ctp < 4; ctp++) {
                const int ct0 = 2 * ctp;
                const uint32_t ba = bufs + bAddrB + ct0 * (8 * ROWB) + kb;
                uint32_t bh[4], bl[4];
                ldsm_x4(bh, ba + B_HI);
                ldsm_x4(bl, ba + B_LO);
                mma_bf16(d[0][ct0],     ah[0], bh[0], bh[1]);
                mma_bf16(d[1][ct0],     ah[1], bh[0], bh[1]);
                mma_bf16(d[0][ct0 + 1], ah[0], bh[2], bh[3]);
                mma_bf16(d[1][ct0 + 1], ah[1], bh[2], bh[3]);
                mma_bf16(d[0][ct0],     al[0], bh[0], bh[1]);
                mma_bf16(d[1][ct0],     al[1], bh[0], bh[1]);
                mma_bf16(d[0][ct0 + 1], al[0], bh[2], bh[3]);
                mma_bf16(d[1][ct0 + 1], al[1], bh[2], bh[3]);
                mma_bf16(d[0][ct0],     ah[0], bl[0], bl[1]);
                mma_bf16(d[1][ct0],     ah[1], bl[0], bl[1]);
                mma_bf16(d[0][ct0 + 1], ah[0], bl[2], bl[3]);
                mma_bf16(d[1][ct0 + 1], ah[1], bl[2], bl[3]);
            }
        }
    }
    __syncthreads();

    float* ep    = (float*)smc;                 // [128][132]
    float* inv_s = (float*)(smc + 67584);       // [128]
    float* l_s   = (float*)(smc + 68096);       // [128]

    if (cw == 0 && tid == 0) {
        l_s[iw * 32 + g]          = dsum[0][0];
        l_s[iw * 32 + g + 8]      = dsum[0][2];
        l_s[iw * 32 + 16 + g]     = dsum[1][0];
        l_s[iw * 32 + 16 + g + 8] = dsum[1][2];
    }
    __syncthreads();
    if (t < 128) inv_s[t] = alphap[0] / l_s[t];

#pragma unroll
    for (int h = 0; h < 2; h++) {
        __syncthreads();
        if ((cw >> 1) == h) {
            const int cb = (cw & 1) * 64;
#pragma unroll
            for (int it = 0; it < 2; it++) {
                const int irow = iw * 32 + it * 16 + g;
#pragma unroll
                for (int ct = 0; ct < 8; ct++) {
                    const int crow = cb + ct * 8 + 2 * tid;
                    ep[crow * 132 + irow]           = d[it][ct][0];
                    ep[(crow + 1) * 132 + irow]     = d[it][ct][1];
                    ep[crow * 132 + irow + 8]       = d[it][ct][2];
                    ep[(crow + 1) * 132 + irow + 8] = d[it][ct][3];
                }
            }
        }
        __syncthreads();
        const int cl0 = t >> 5;
        const int i4  = (t & 31) * 4;
        const float4 iv = *(const float4*)&inv_s[i4];
#pragma unroll
        for (int p = 0; p < 8; p++) {
            const int cloc = cl0 + p * 16;
            float4 v = *(const float4*)&ep[cloc * 132 + i4];
            const size_t o = ((size_t)(n * CHN) + h * 128 + cloc) * NHW + i0 + i4;
            float4 av = *(const float4*)(a + o);
            *(float4*)(out + o) = make_float4(fmaf(iv.x, v.x, av.x),
                                              fmaf(iv.y, v.y, av.y),
                                              fmaf(iv.z, v.z, av.z),
                                              fmaf(iv.w, v.w, av.w));
        }
    }
}

// ---------------------------------------------------------------------------
extern "C" void kernel_launch(void* const* d_in, const int* in_sizes, int n_in,
                              void* d_out, int out_size)
{
    const float* a     = (const float*)d_in[0];
    const float* b_w   = (const float*)d_in[1];
    const float* b_b   = (const float*)d_in[2];
    const float* c_w   = (const float*)d_in[3];
    const float* c_b   = (const float*)d_in[4];
    const float* d_w   = (const float*)d_in[5];
    const float* d_b   = (const float*)d_in[6];
    const float* alpha = (const float*)d_in[7];
    float* out = (float*)d_out;

    cudaFuncSetAttribute(k3_mma, cudaFuncAttributeMaxDynamicSharedMemorySize, K3_SMEM);

    k1_conv<<<dim3(8, 20, 4), 256>>>(a, b_w, b_b, c_w, c_b, d_w, d_b);
    k2_scores<<<dim3(32, 32, 4), 256>>>();
    k3_mma<<<dim3(32, 4), 512, K3_SMEM>>>(a, alpha, out);
}

// round 17
// speedup vs baseline: 1.0805x; 1.0270x over previous
#include <cuda_runtime.h>
#include <cuda_bf16.h>
#include <math.h>
#include <stdint.h>

#define NB   4
#define CHN  256
#define NHW  4096
#define MALL 320   // 32 (b) + 32 (c) + 256 (d)

// ---- scratch (device globals -- allocation is forbidden) ----
__device__ float         g_bcd[(size_t)NB * NHW * MALL];  // [n][i][320] (b,c used)
__device__ __nv_bfloat16 g_Phi[(size_t)NB * NHW * NHW];   // exp(s) hi (row-major)
__device__ __nv_bfloat16 g_Plo[(size_t)NB * NHW * NHW];   // exp(s) lo (row-major)
__device__ __nv_bfloat16 g_dhi[(size_t)NB * CHN * NHW];   // d^T hi  [n][c][j]
__device__ __nv_bfloat16 g_dlo[(size_t)NB * CHN * NHW];   // d^T lo

typedef unsigned long long ull;

__device__ __forceinline__ void cp_async16(uint32_t dst, const void* src) {
    asm volatile("cp.async.cg.shared.global [%0], [%1], 16;" :: "r"(dst), "l"(src));
}
#define CP_COMMIT() asm volatile("cp.async.commit_group;")
#define CP_WAIT0()  asm volatile("cp.async.wait_group 0;" ::: "memory")
#define CP_WAIT1()  asm volatile("cp.async.wait_group 1;" ::: "memory")

// warp-level bf16 tensor-core mma (baseline PTX, valid on sm_103 non-'a')
__device__ __forceinline__ void mma_bf16(float* d, const uint32_t* A,
                                         uint32_t b0, uint32_t b1) {
    asm volatile(
        "mma.sync.aligned.m16n8k16.row.col.f32.bf16.bf16.f32 "
        "{%0,%1,%2,%3}, {%4,%5,%6,%7}, {%8,%9}, {%0,%1,%2,%3};"
        : "+f"(d[0]), "+f"(d[1]), "+f"(d[2]), "+f"(d[3])
        : "r"(A[0]), "r"(A[1]), "r"(A[2]), "r"(A[3]), "r"(b0), "r"(b1));
}
__device__ __forceinline__ void ldsm_x4(uint32_t* r, uint32_t addr) {
    asm volatile("ldmatrix.sync.aligned.m8n8.x4.shared.b16 {%0,%1,%2,%3}, [%4];"
        : "=r"(r[0]), "=r"(r[1]), "=r"(r[2]), "=r"(r[3]) : "r"(addr));
}
__device__ __forceinline__ void ldsm_x4_t(uint32_t* r, uint32_t addr) {
    asm volatile("ldmatrix.sync.aligned.m8n8.x4.trans.shared.b16 {%0,%1,%2,%3}, [%4];"
        : "=r"(r[0]), "=r"(r[1]), "=r"(r[2]), "=r"(r[3]) : "r"(addr));
}
__device__ __forceinline__ uint32_t bf16x2(float x, float y) {
    union { __nv_bfloat16 b[2]; uint32_t u; } p;
    p.b[0] = __float2bfloat16(x);
    p.b[1] = __float2bfloat16(y);
    return p.u;
}

// ---------------------------------------------------------------------------
// K1: fused 1x1 convs on tensor cores (bf16 hi/lo 3-split).
// CTA: 320 m x 64 px, K=256 in 8 chunks of 32, double-buffered staging.
// A = W [m][ch] (non-trans ldsm, ROWB 80), B = a [ch][px] (trans ldsm, 144).
// Epilogue: m<64 -> fp32 g_bcd; m>=64 -> bf16 hi/lo d^T.  Grid (64, 4).
// ---------------------------------------------------------------------------
#define K1_WROW 80
#define K1_AROW 144
#define K1_WH   0
#define K1_WL   25600
#define K1_AH   51200
#define K1_AL   55808
#define K1_BUF  60416
#define K1_SMEM (2 * K1_BUF + 1280)

__global__ __launch_bounds__(512, 1) void k1_tensor(
    const float* __restrict__ a,
    const float* __restrict__ b_w, const float* __restrict__ b_b,
    const float* __restrict__ c_w, const float* __restrict__ c_b,
    const float* __restrict__ d_w, const float* __restrict__ d_b)
{
    extern __shared__ __align__(16) char smc[];
    const uint32_t smb = (uint32_t)__cvta_generic_to_shared(smc);

    const int t    = threadIdx.x;
    const int lane = t & 31;
    const int warp = t >> 5;
    const int g    = lane >> 2;
    const int tid  = lane & 3;
    const int wm   = warp & 3;      // m group of 80
    const int wp   = warp >> 2;     // px group of 16
    const int n    = blockIdx.y;
    const int px0  = blockIdx.x * 64;

    float* bias_s = (float*)(smc + 2 * K1_BUF);
    if (t < 320)
        bias_s[t] = (t < 32) ? b_b[t] : (t < 64) ? c_b[t - 32] : d_b[t - 64];

    float d[5][2][4];
#pragma unroll
    for (int it = 0; it < 5; it++)
#pragma unroll
        for (int jt = 0; jt < 2; jt++)
#pragma unroll
            for (int r = 0; r < 4; r++) d[it][jt][r] = 0.0f;

    // per-thread staging constants
    const int ach  = t >> 4, apart = t & 15;              // a: ch row, px part
    const float* asrc = a + ((size_t)(n * CHN) + ach) * NHW + px0 + apart * 4;

#define K1_STAGE(kc, buf)                                                     \
    do {                                                                      \
        const int ch0_ = (kc) * 32;                                           \
        if (t < 320) {                                                        \
            const int m_ = t;                                                 \
            const float* wr_ = (m_ < 32) ? (b_w + m_ * 256)                   \
                             : (m_ < 64) ? (c_w + (m_ - 32) * 256)            \
                                         : (d_w + (m_ - 64) * 256);           \
            const float4* ws_ = (const float4*)(wr_ + ch0_);                  \
            char* whp_ = (buf) + K1_WH + m_ * K1_WROW;                        \
            char* wlp_ = (buf) + K1_WL + m_ * K1_WROW;                        \
            _Pragma("unroll")                                                 \
            for (int q_ = 0; q_ < 4; q_++) {                                  \
                float4 v0_ = ws_[2 * q_], v1_ = ws_[2 * q_ + 1];              \
                float f_[8] = {v0_.x, v0_.y, v0_.z, v0_.w,                    \
                               v1_.x, v1_.y, v1_.z, v1_.w};                   \
                union { __nv_bfloat16 b[8]; uint4 u; } H_, L_;                \
                _Pragma("unroll")                                             \
                for (int k_ = 0; k_ < 8; k_++) {                              \
                    H_.b[k_] = __float2bfloat16(f_[k_]);                      \
                    L_.b[k_] = __float2bfloat16(f_[k_] -                      \
                                   __bfloat162float(H_.b[k_]));               \
                }                                                             \
                *(uint4*)(whp_ + q_ * 16) = H_.u;                             \
                *(uint4*)(wlp_ + q_ * 16) = L_.u;                             \
            }                                                                 \
        }                                                                     \
        {                                                                     \
            float4 v_ = *(const float4*)(asrc + (size_t)ch0_ * NHW);          \
            __nv_bfloat16 h0_ = __float2bfloat16(v_.x);                       \
            __nv_bfloat16 h1_ = __float2bfloat16(v_.y);                       \
            __nv_bfloat16 h2_ = __float2bfloat16(v_.z);                       \
            __nv_bfloat16 h3_ = __float2bfloat16(v_.w);                       \
            union { __nv_bfloat16 b[4]; uint2 u; } HA_, LA_;                  \
            HA_.b[0] = h0_; HA_.b[1] = h1_; HA_.b[2] = h2_; HA_.b[3] = h3_;   \
            LA_.b[0] = __float2bfloat16(v_.x - __bfloat162float(h0_));        \
            LA_.b[1] = __float2bfloat16(v_.y - __bfloat162float(h1_));        \
            LA_.b[2] = __float2bfloat16(v_.z - __bfloat162float(h2_));        \
            LA_.b[3] = __float2bfloat16(v_.w - __bfloat162float(h3_));        \
            *(uint2*)((buf) + K1_AH + ach * K1_AROW + apart * 8) = HA_.u;     \
            *(uint2*)((buf) + K1_AL + ach * K1_AROW + apart * 8) = LA_.u;     \
        }                                                                     \
    } while (0)

    K1_STAGE(0, smc);

    const uint32_t bofsL = (uint32_t)(((lane & 7) + ((lane >> 3) & 1) * 8) * K1_AROW
                                      + wp * 32 + (lane >> 4) * 16);
    const uint32_t aofsL = (uint32_t)((wm * 80 + (lane & 15)) * K1_WROW
                                      + (lane >> 4) * 16);

    for (int kc = 0; kc < 8; kc++) {
        __syncthreads();
        if (kc + 1 < 8) K1_STAGE(kc + 1, smc + ((kc + 1) & 1) * K1_BUF);

        const uint32_t bb = smb + (kc & 1) * K1_BUF;
#pragma unroll
        for (int k16 = 0; k16 < 2; k16++) {
            uint32_t bh[4], bl[4];
            const uint32_t ba = bb + bofsL + (uint32_t)(k16 * 16 * K1_AROW);
            ldsm_x4_t(bh, ba + K1_AH);
            ldsm_x4_t(bl, ba + K1_AL);
#pragma unroll
            for (int it = 0; it < 5; it++) {
                uint32_t wh[4], wl[4];
                const uint32_t wa = bb + aofsL + (uint32_t)(it * 16 * K1_WROW)
                                    + (uint32_t)(k16 * 32);
                ldsm_x4(wh, wa + K1_WH);
                ldsm_x4(wl, wa + K1_WL);
                mma_bf16(d[it][0], wh, bh[0], bh[1]);
                mma_bf16(d[it][1], wh, bh[2], bh[3]);
                mma_bf16(d[it][0], wl, bh[0], bh[1]);
                mma_bf16(d[it][1], wl, bh[2], bh[3]);
                mma_bf16(d[it][0], wh, bl[0], bl[1]);
                mma_bf16(d[it][1], wh, bl[2], bl[3]);
            }
        }
    }
#undef K1_STAGE

    // epilogue
#pragma unroll
    for (int it = 0; it < 5; it++) {
        const int m0 = wm * 80 + it * 16 + g;
        const float b0 = bias_s[m0], b1 = bias_s[m0 + 8];
#pragma unroll
        for (int jt = 0; jt < 2; jt++) {
            const int px = px0 + wp * 16 + jt * 8 + 2 * tid;
            const float v00 = d[it][jt][0] + b0;
            const float v01 = d[it][jt][1] + b0;
            const float v10 = d[it][jt][2] + b1;
            const float v11 = d[it][jt][3] + b1;
            if (m0 < 64) {
                const size_t r0 = ((size_t)(n * NHW) + px) * MALL;
                g_bcd[r0 + m0]            = v00;
                g_bcd[r0 + MALL + m0]     = v01;
                g_bcd[r0 + m0 + 8]        = v10;
                g_bcd[r0 + MALL + m0 + 8] = v11;
            } else {
                const int c = m0 - 64;
                const size_t o0 = ((size_t)(n * CHN) + c) * NHW + px;
                const size_t o1 = o0 + (size_t)8 * NHW;
                __nv_bfloat16 h00 = __float2bfloat16(v00);
                __nv_bfloat16 h01 = __float2bfloat16(v01);
                __nv_bfloat16 h10 = __float2bfloat16(v10);
                __nv_bfloat16 h11 = __float2bfloat16(v11);
                union { __nv_bfloat16 b[2]; uint32_t u; } p;
                p.b[0] = h00; p.b[1] = h01; *(uint32_t*)(g_dhi + o0) = p.u;
                p.b[0] = h10; p.b[1] = h11; *(uint32_t*)(g_dhi + o1) = p.u;
                p.b[0] = __float2bfloat16(v00 - __bfloat162float(h00));
                p.b[1] = __float2bfloat16(v01 - __bfloat162float(h01));
                *(uint32_t*)(g_dlo + o0) = p.u;
                p.b[0] = __float2bfloat16(v10 - __bfloat162float(h10));
                p.b[1] = __float2bfloat16(v11 - __bfloat162float(h11));
                *(uint32_t*)(g_dlo + o1) = p.u;
            }
        }
    }
}

// ---------------------------------------------------------------------------
// K2: scores via tensor cores (bf16 hi/lo 3-split, K=32) + fused exp.
// Epilogue: per-warp smem transpose -> 16B/lane stores, full 32B sectors.
// 256 thr / 8 warps, tile 128i x 128j.  Grid (32 j-tiles, 32 i-tiles, 4).
// ---------------------------------------------------------------------------
#define K2RB 80    // 64B data + 16B pad: LDSM conflict-free
#define WROW 144   // per-warp epilogue row stride

__global__ __launch_bounds__(256) void k2_scores()
{
    __shared__ __align__(16) char sm2[4 * 128 * K2RB];   // 40960 B
    const uint32_t smb = (uint32_t)__cvta_generic_to_shared(sm2);
    const int AHI = 0, ALO = 10240, BHI = 20480, BLO = 30720;

    const int t    = threadIdx.x;
    const int lane = t & 31;
    const int warp = t >> 5;
    const int g    = lane >> 2;
    const int tid  = lane & 3;
    const int iw   = warp & 3;
    const int cw   = warp >> 2;
    const int n    = blockIdx.z;
    const int i0   = blockIdx.y * 128;
    const int j0   = blockIdx.x * 128;

    {
        const int r  = t >> 1;
        const int hb = t & 1;
        const float* qs = g_bcd + ((size_t)(n * NHW) + i0 + r) * MALL + hb * 16;
        const float* cs = g_bcd + ((size_t)(n * NHW) + j0 + r) * MALL + 32 + hb * 16;
        const uint32_t dst = (uint32_t)(r * K2RB + hb * 32);
#pragma unroll
        for (int sel = 0; sel < 2; sel++) {
            const float* src = sel ? cs : qs;
            const int OH = sel ? BHI : AHI;
            const int OL = sel ? BLO : ALO;
#pragma unroll
            for (int q = 0; q < 2; q++) {
                float4 v0 = *(const float4*)(src + q * 8);
                float4 v1 = *(const float4*)(src + q * 8 + 4);
                float f[8] = {v0.x, v0.y, v0.z, v0.w, v1.x, v1.y, v1.z, v1.w};
                union { __nv_bfloat16 b[8]; uint4 u; } H, L;
#pragma unroll
                for (int k = 0; k < 8; k++) {
                    H.b[k] = __float2bfloat16(f[k]);
                    L.b[k] = __float2bfloat16(f[k] - __bfloat162float(H.b[k]));
                }
                *(uint4*)(sm2 + OH + dst + q * 16) = H.u;
                *(uint4*)(sm2 + OL + dst + q * 16) = L.u;
            }
        }
    }
    __syncthreads();

    const uint32_t aAddr = smb + (uint32_t)((iw * 32 + (lane & 15)) * K2RB + (lane >> 4) * 16);
    const uint32_t bAddr = smb + (uint32_t)((cw * 64 + (lane >> 4) * 8 + (lane & 7)) * K2RB
                                            + ((lane >> 3) & 1) * 16);
    float d[2][8][4];
#pragma unroll
    for (int it = 0; it < 2; it++)
#pragma unroll
        for (int jt = 0; jt < 8; jt++)
#pragma unroll
            for (int r = 0; r < 4; r++) d[it][jt][r] = 0.0f;

#pragma unroll
    for (int ks = 0; ks < 2; ks++) {
        const uint32_t kb = ks * 32;
        uint32_t ah[2][4], al[2][4];
#pragma unroll
        for (int it = 0; it < 2; it++) {
            const uint32_t aa = aAddr + it * (16 * K2RB) + kb;
            ldsm_x4(ah[it], aa + AHI);
            ldsm_x4(al[it], aa + ALO);
        }
#pragma unroll
        for (int ctp = 0; ctp < 4; ctp++) {
            const int ct0 = 2 * ctp;
            const uint32_t ba = bAddr + ct0 * (8 * K2RB) + kb;
            uint32_t bh[4], bl[4];
            ldsm_x4(bh, ba + BHI);
            ldsm_x4(bl, ba + BLO);
            mma_bf16(d[0][ct0],     ah[0], bh[0], bh[1]);
            mma_bf16(d[1][ct0],     ah[1], bh[0], bh[1]);
            mma_bf16(d[0][ct0 + 1], ah[0], bh[2], bh[3]);
            mma_bf16(d[1][ct0 + 1], ah[1], bh[2], bh[3]);
            mma_bf16(d[0][ct0],     al[0], bh[0], bh[1]);
            mma_bf16(d[1][ct0],     al[1], bh[0], bh[1]);
            mma_bf16(d[0][ct0 + 1], al[0], bh[2], bh[3]);
            mma_bf16(d[1][ct0 + 1], al[1], bh[2], bh[3]);
            mma_bf16(d[0][ct0],     ah[0], bl[0], bl[1]);
            mma_bf16(d[1][ct0],     ah[1], bl[0], bl[1]);
            mma_bf16(d[0][ct0 + 1], ah[0], bl[2], bl[3]);
            mma_bf16(d[1][ct0 + 1], ah[1], bl[2], bl[3]);
        }
    }
    __syncthreads();

    char* ws = sm2 + warp * (16 * WROW);
    const int rrow = lane >> 1;
    const int rch  = lane & 1;
    const size_t gi = (size_t)(n * NHW) + i0 + iw * 32;
    const int    gj = j0 + cw * 64;

#pragma unroll
    for (int it = 0; it < 2; it++) {
        uint32_t vh[2][8], vl[2][8];
#pragma unroll
        for (int jt = 0; jt < 8; jt++) {
            float e0 = __expf(d[it][jt][0]);
            float e1 = __expf(d[it][jt][1]);
            float e2 = __expf(d[it][jt][2]);
            float e3 = __expf(d[it][jt][3]);
            union { __nv_bfloat16 b[2]; uint32_t u; } p;
            __nv_bfloat16 h0 = __float2bfloat16(e0);
            __nv_bfloat16 h1 = __float2bfloat16(e1);
            __nv_bfloat16 h2 = __float2bfloat16(e2);
            __nv_bfloat16 h3 = __float2bfloat16(e3);
            p.b[0] = h0; p.b[1] = h1; vh[0][jt] = p.u;
            p.b[0] = h2; p.b[1] = h3; vh[1][jt] = p.u;
            p.b[0] = __float2bfloat16(e0 - __bfloat162float(h0));
            p.b[1] = __float2bfloat16(e1 - __bfloat162float(h1));
            vl[0][jt] = p.u;
            p.b[0] = __float2bfloat16(e2 - __bfloat162float(h2));
            p.b[1] = __float2bfloat16(e3 - __bfloat162float(h3));
            vl[1][jt] = p.u;
        }
#pragma unroll
        for (int hl = 0; hl < 2; hl++) {
#pragma unroll
            for (int rs = 0; rs < 2; rs++) {
                const int row = g + 8 * rs;
#pragma unroll
                for (int jt = 0; jt < 8; jt++) {
                    uint32_t v = hl ? vl[rs][jt] : vh[rs][jt];
                    *(uint32_t*)(ws + row * WROW + jt * 16 + tid * 4) = v;
                }
            }
            __syncwarp();
            __nv_bfloat16* gdst = hl ? g_Plo : g_Phi;
#pragma unroll
            for (int pass = 0; pass < 4; pass++) {
                const int ch = pass * 2 + rch;
                uint4 v = *(const uint4*)(ws + rrow * WROW + ch * 16);
                *(uint4*)(gdst + (gi + it * 16 + rrow) * NHW + gj + ch * 8) = v;
            }
            __syncwarp();
        }
    }
}

// ---------------------------------------------------------------------------
// K3: tensor-core PV GEMM via mma.sync + ldmatrix (bf16 hi/lo split),
// fused row-sum via all-ones B.  KT=64, double buffer (216KB smem),
// 512 thr / 16 warps, tile 128i x 256c.  Grid (32 i-tiles, 4 batches).
// ---------------------------------------------------------------------------
#define KT      64
#define NSTG    (NHW / KT)
#define ROWB    144
#define A_HI    0
#define A_LO    18432
#define B_HI    36864
#define B_LO    73728
#define STG     110592
#define K3_SMEM (2 * STG)

__global__ __launch_bounds__(512, 1) void k3_mma(
    const float* __restrict__ a,
    const float* __restrict__ alphap,
    float* __restrict__ out)
{
    extern __shared__ __align__(16) char smc[];
    const uint32_t smb = (uint32_t)__cvta_generic_to_shared(smc);

    const int t    = threadIdx.x;
    const int lane = t & 31;
    const int warp = t >> 5;
    const int g    = lane >> 2;
    const int tid  = lane & 3;
    const int iw   = warp & 3;
    const int cw   = warp >> 2;
    const int n    = blockIdx.y;
    const int i0   = blockIdx.x * 128;

    const __nv_bfloat16* Phi = g_Phi + (size_t)(n * NHW + i0) * NHW;
    const __nv_bfloat16* Plo = g_Plo + (size_t)(n * NHW + i0) * NHW;
    const __nv_bfloat16* Dhi = g_dhi + (size_t)n * CHN * NHW;
    const __nv_bfloat16* Dlo = g_dlo + (size_t)n * CHN * NHW;

    uint32_t aoff[2], agl[2], boff[4], bgl[4];
#pragma unroll
    for (int q = 0; q < 2; q++) {
        int idx = t + q * 512, row = idx >> 3, col = idx & 7;
        aoff[q] = (uint32_t)(row * ROWB + col * 16);
        agl[q]  = (uint32_t)(row * NHW + col * 8);
    }
#pragma unroll
    for (int q = 0; q < 4; q++) {
        int idx = t + q * 512, row = idx >> 3, col = idx & 7;
        boff[q] = (uint32_t)(row * ROWB + col * 16);
        bgl[q]  = (uint32_t)(row * NHW + col * 8);
    }

    const uint32_t aAddr0 = (uint32_t)((iw * 32 + (lane & 15)) * ROWB + (lane >> 4) * 16);
    const uint32_t bAddrB = (uint32_t)((cw * 64 + (lane >> 4) * 8 + (lane & 7)) * ROWB
                                       + ((lane >> 3) & 1) * 16);

    float d[2][8][4];
#pragma unroll
    for (int it = 0; it < 2; it++)
#pragma unroll
        for (int ct = 0; ct < 8; ct++)
#pragma unroll
            for (int r = 0; r < 4; r++) d[it][ct][r] = 0.0f;

    float dsum[2][4];
#pragma unroll
    for (int it = 0; it < 2; it++)
#pragma unroll
        for (int r = 0; r < 4; r++) dsum[it][r] = 0.0f;
    const uint32_t ONES = 0x3F803F80u;

    {
        const uint32_t bb = smb;
#pragma unroll
        for (int q = 0; q < 2; q++) cp_async16(bb + A_HI + aoff[q], Phi + agl[q]);
#pragma unroll
        for (int q = 0; q < 2; q++) cp_async16(bb + A_LO + aoff[q], Plo + agl[q]);
#pragma unroll
        for (int q = 0; q < 4; q++) cp_async16(bb + B_HI + boff[q], Dhi + bgl[q]);
#pragma unroll
        for (int q = 0; q < 4; q++) cp_async16(bb + B_LO + boff[q], Dlo + bgl[q]);
        CP_COMMIT();
    }

    for (int s = 0; s < NSTG; ++s) {
        if (s + 1 < NSTG) {
            __syncthreads();
            const uint32_t bb = smb + ((s + 1) & 1) * STG;
            const uint32_t jt = (uint32_t)(s + 1) * KT;
#pragma unroll
            for (int q = 0; q < 2; q++) cp_async16(bb + A_HI + aoff[q], Phi + agl[q] + jt);
#pragma unroll
            for (int q = 0; q < 2; q++) cp_async16(bb + A_LO + aoff[q], Plo + agl[q] + jt);
#pragma unroll
            for (int q = 0; q < 4; q++) cp_async16(bb + B_HI + boff[q], Dhi + bgl[q] + jt);
#pragma unroll
            for (int q = 0; q < 4; q++) cp_async16(bb + B_LO + boff[q], Dlo + bgl[q] + jt);
            CP_COMMIT();
            CP_WAIT1();
        } else {
            CP_WAIT0();
        }
        __syncthreads();

        const uint32_t bufs = smb + (s & 1) * STG;

#pragma unroll
        for (int ks = 0; ks < 4; ks++) {
            const uint32_t kb = ks * 32;
            uint32_t ah[2][4], al[2][4];
#pragma unroll
            for (int it = 0; it < 2; it++) {
                const uint32_t aa = bufs + aAddr0 + it * (16 * ROWB) + kb;
                ldsm_x4(ah[it], aa + A_HI);
                ldsm_x4(al[it], aa + A_LO);
            }
            if (cw == 0) {
                mma_bf16(dsum[0], ah[0], ONES, ONES);
                mma_bf16(dsum[0], al[0], ONES, ONES);
                mma_bf16(dsum[1], ah[1], ONES, ONES);
                mma_bf16(dsum[1], al[1], ONES, ONES);
            }
#pragma unroll
            for (int ctp = 0; ctp < 4; ctp++) {
                const int ct0 = 2 * ctp;
                const uint32_t ba = bufs + bAddrB + ct0 * (8 * ROWB) + kb;
                uint32_t bh[4], bl[4];
                ldsm_x4(bh, ba + B_HI);
                ldsm_x4(bl, ba + B_LO);
                mma_bf16(d[0][ct0],     ah[0], bh[0], bh[1]);
                mma_bf16(d[1][ct0],     ah[1], bh[0], bh[1]);
                mma_bf16(d[0][ct0 + 1], ah[0], bh[2], bh[3]);
                mma_bf16(d[1][ct0 + 1], ah[1], bh[2], bh[3]);
                mma_bf16(d[0][ct0],     al[0], bh[0], bh[1]);
                mma_bf16(d[1][ct0],     al[1], bh[0], bh[1]);
                mma_bf16(d[0][ct0 + 1], al[0], bh[2], bh[3]);
                mma_bf16(d[1][ct0 + 1], al[1], bh[2], bh[3]);
                mma_bf16(d[0][ct0],     ah[0], bl[0], bl[1]);
                mma_bf16(d[1][ct0],     ah[1], bl[0], bl[1]);
                mma_bf16(d[0][ct0 + 1], ah[0], bl[2], bl[3]);
                mma_bf16(d[1][ct0 + 1], ah[1], bl[2], bl[3]);
            }
        }
    }
    __syncthreads();

    float* ep    = (float*)smc;
    float* inv_s = (float*)(smc + 67584);
    float* l_s   = (float*)(smc + 68096);

    if (cw == 0 && tid == 0) {
        l_s[iw * 32 + g]          = dsum[0][0];
        l_s[iw * 32 + g + 8]      = dsum[0][2];
        l_s[iw * 32 + 16 + g]     = dsum[1][0];
        l_s[iw * 32 + 16 + g + 8] = dsum[1][2];
    }
    __syncthreads();
    if (t < 128) inv_s[t] = alphap[0] / l_s[t];

#pragma unroll
    for (int h = 0; h < 2; h++) {
        __syncthreads();
        if ((cw >> 1) == h) {
            const int cb = (cw & 1) * 64;
#pragma unroll
            for (int it = 0; it < 2; it++) {
                const int irow = iw * 32 + it * 16 + g;
#pragma unroll
                for (int ct = 0; ct < 8; ct++) {
                    const int crow = cb + ct * 8 + 2 * tid;
                    ep[crow * 132 + irow]           = d[it][ct][0];
                    ep[(crow + 1) * 132 + irow]     = d[it][ct][1];
                    ep[crow * 132 + irow + 8]       = d[it][ct][2];
                    ep[(crow + 1) * 132 + irow + 8] = d[it][ct][3];
                }
            }
        }
        __syncthreads();
        const int cl0 = t >> 5;
        const int i4  = (t & 31) * 4;
        const float4 iv = *(const float4*)&inv_s[i4];
#pragma unroll
        for (int p = 0; p < 8; p++) {
            const int cloc = cl0 + p * 16;
            float4 v = *(const float4*)&ep[cloc * 132 + i4];
            const size_t o = ((size_t)(n * CHN) + h * 128 + cloc) * NHW + i0 + i4;
            float4 av = *(const float4*)(a + o);
            *(float4*)(out + o) = make_float4(fmaf(iv.x, v.x, av.x),
                                              fmaf(iv.y, v.y, av.y),
                                              fmaf(iv.z, v.z, av.z),
                                              fmaf(iv.w, v.w, av.w));
        }
    }
}

// ---------------------------------------------------------------------------
extern "C" void kernel_launch(void* const* d_in, const int* in_sizes, int n_in,
                              void* d_out, int out_size)
{
    const float* a     = (const float*)d_in[0];
    const float* b_w   = (const float*)d_in[1];
    const float* b_b   = (const float*)d_in[2];
    const float* c_w   = (const float*)d_in[3];
    const float* c_b   = (const float*)d_in[4];
    const float* d_w   = (const float*)d_in[5];
    const float* d_b   = (const float*)d_in[6];
    const float* alpha = (const float*)d_in[7];
    float* out = (float*)d_out;

    cudaFuncSetAttribute(k1_tensor, cudaFuncAttributeMaxDynamicSharedMemorySize, K1_SMEM);
    cudaFuncSetAttribute(k3_mma,    cudaFuncAttributeMaxDynamicSharedMemorySize, K3_SMEM);

    k1_tensor<<<dim3(64, 4), 512, K1_SMEM>>>(a, b_w, b_b, c_w, c_b, d_w, d_b);
    k2_scores<<<dim3(32, 32, 4), 256>>>();
    k3_mma<<<dim3(32, 4), 512, K3_SMEM>>>(a, alpha, out);
}